// round 14
// baseline (speedup 1.0000x reference)
#include <cuda_runtime.h>
#include <cuda_fp16.h>
#include <cstdint>
#include <math.h>

#define HID    1024
#define INTER  4096
#define NTOK   4096
#define NKEYS  64
#define TOPK   8

typedef unsigned short u16;
typedef unsigned int   u32;

// ---------------- scratch (no allocations allowed) ----------------
__device__ __align__(16) static u16   g_Xh[(size_t)NTOK * HID];
__device__ __align__(16) static u16   g_Xl[(size_t)NTOK * HID];
__device__ __align__(16) static u16   g_Wgh[(size_t)INTER * HID];
__device__ __align__(16) static u16   g_Wuh[(size_t)INTER * HID];
__device__ __align__(16) static u16   g_Wdh[(size_t)HID * INTER];
__device__ __align__(16) static u16   g_Wrh[(size_t)128 * HID];
__device__ __align__(16) static u16   g_Wrl[(size_t)128 * HID];
__device__ __align__(16) static u16   g_Hh[(size_t)NTOK * INTER];
__device__ static u32   g_done_gu;
__device__ static u32   g_done_r;

// ---------------- helpers ----------------
__device__ __forceinline__ u32 smem_u32(const void* p) {
    u32 a;
    asm("{ .reg .u64 t; cvta.to.shared.u64 t, %1; cvt.u32.u64 %0, t; }" : "=r"(a) : "l"(p));
    return a;
}

__device__ __forceinline__ void cp16(u32 dst, const void* src) {
    asm volatile("cp.async.cg.shared.global [%0], [%1], 16;" :: "r"(dst), "l"(src));
}
#define CP_COMMIT() asm volatile("cp.async.commit_group;" ::: "memory")
#define CP_WAIT(n)  asm volatile("cp.async.wait_group %0;" :: "n"(n) : "memory")

__device__ __forceinline__ void ldsm_x4(u32& r0, u32& r1, u32& r2, u32& r3, u32 addr) {
    asm volatile("ldmatrix.sync.aligned.m8n8.x4.shared.b16 {%0,%1,%2,%3}, [%4];"
                 : "=r"(r0), "=r"(r1), "=r"(r2), "=r"(r3) : "r"(addr));
}
__device__ __forceinline__ void ldsm_x2(u32& r0, u32& r1, u32 addr) {
    asm volatile("ldmatrix.sync.aligned.m8n8.x2.shared.b16 {%0,%1}, [%2];"
                 : "=r"(r0), "=r"(r1) : "r"(addr));
}

__device__ __forceinline__ void mma_f32(float* c, const u32* a, const u32* b) {
    asm volatile(
        "mma.sync.aligned.m16n8k16.row.col.f32.f16.f16.f32 "
        "{%0,%1,%2,%3}, {%4,%5,%6,%7}, {%8,%9}, {%0,%1,%2,%3};"
        : "+f"(c[0]), "+f"(c[1]), "+f"(c[2]), "+f"(c[3])
        : "r"(a[0]), "r"(a[1]), "r"(a[2]), "r"(a[3]), "r"(b[0]), "r"(b[1]));
}
__device__ __forceinline__ void mma_f16(u32* c, const u32* a, const u32* b) {
    asm volatile(
        "mma.sync.aligned.m16n8k16.row.col.f16.f16.f16.f16 "
        "{%0,%1}, {%2,%3,%4,%5}, {%6,%7}, {%0,%1};"
        : "+r"(c[0]), "+r"(c[1])
        : "r"(a[0]), "r"(a[1]), "r"(a[2]), "r"(a[3]), "r"(b[0]), "r"(b[1]));
}

__device__ __forceinline__ float silu(float x) { return x / (1.f + expf(-x)); }

// =====================================================================
// split_all_kernel: one launch, grid 20608.
// [0,4096): X split2 ; [4096,4224): Wr split2 ;
// [4224,8320): Wg ; [8320,12416): Wu ; [12416,16512): Wd (split1) ;
// [16512,20608): zero out.  Block 0 also resets the dataflow counters.
// =====================================================================
__global__ void split_all_kernel(const float* __restrict__ X,
                                 const float* __restrict__ Wr,
                                 const float* __restrict__ Wg,
                                 const float* __restrict__ Wu,
                                 const float* __restrict__ Wd,
                                 u16* __restrict__ Xh, u16* __restrict__ Xl,
                                 u16* __restrict__ Wrh, u16* __restrict__ Wrl,
                                 u16* __restrict__ Wgh, u16* __restrict__ Wuh,
                                 u16* __restrict__ Wdh,
                                 float* __restrict__ out)
{
    const int b = blockIdx.x;
    const int tid = threadIdx.x;
    if (b == 0 && tid == 0) { g_done_gu = 0u; g_done_r = 0u; }

    if (b < 4224) {
        const float* src; u16 *hi, *lo; int i;
        if (b < 4096) { src = X;  hi = Xh;  lo = Xl;  i = b * 256 + tid; }
        else          { src = Wr; hi = Wrh; lo = Wrl; i = (b - 4096) * 256 + tid; }
        float4 v = ((const float4*)src)[i];
        __half hx = __float2half_rn(v.x), hy = __float2half_rn(v.y);
        __half hz = __float2half_rn(v.z), hw = __float2half_rn(v.w);
        __half lx = __float2half_rn(v.x - __half2float(hx));
        __half ly = __float2half_rn(v.y - __half2float(hy));
        __half lz = __float2half_rn(v.z - __half2float(hz));
        __half lw = __float2half_rn(v.w - __half2float(hw));
        __half2 h0 = __halves2half2(hx, hy), h1 = __halves2half2(hz, hw);
        __half2 l0 = __halves2half2(lx, ly), l1 = __halves2half2(lz, lw);
        ((uint2*)hi)[i] = make_uint2(*(u32*)&h0, *(u32*)&h1);
        ((uint2*)lo)[i] = make_uint2(*(u32*)&l0, *(u32*)&l1);
    } else if (b < 16512) {
        const float* src; u16* dst; int i;
        if (b < 8320)       { src = Wg; dst = Wgh; i = (b - 4224) * 256 + tid; }
        else if (b < 12416) { src = Wu; dst = Wuh; i = (b - 8320) * 256 + tid; }
        else                { src = Wd; dst = Wdh; i = (b - 12416) * 256 + tid; }
        float4 v = ((const float4*)src)[i];
        __half2 h0 = __halves2half2(__float2half_rn(v.x), __float2half_rn(v.y));
        __half2 h1 = __halves2half2(__float2half_rn(v.z), __float2half_rn(v.w));
        ((uint2*)dst)[i] = make_uint2(*(u32*)&h0, *(u32*)&h1);
    } else {
        ((float4*)out)[(b - 16512) * 256 + tid] = make_float4(0.f, 0.f, 0.f, 0.f);
    }
}

#define PITCH 80
#define PLANE128 10240                // 128 rows * 80
#define PLANE64  5120                 // 64 rows * 80
#define STG_GU 20480                  // GU & down stage (3 stages = 61440)
#define STG_R  30720                  // router stage (2 stages = 61440)
#define SMEM_MEGA 61440

__device__ __forceinline__ void top8_insert(float v, int idx, float* hv, int* hi) {
    if (v <= hv[7]) return;
    int p = 7;
    #pragma unroll
    for (int q = 7; q > 0; q--) {
        if (v > hv[q-1]) { hv[q] = hv[q-1]; hi[q] = hi[q-1]; p = q - 1; }
    }
    hv[p] = v; hi[p] = idx;
}

// =====================================================================
// mega_kernel: grid 6464, 256 thr, occ 2, smem 61440.
//  [0,2048)    : gate/up GU tile 128x64 -> Hh ; release g_done_gu
//  [2048,2112) : router fp16x3 tile 128x64 -> logits ; release g_done_r
//  [2112,2368) : down tile 128x128 (3-stage) ; acquire g_done_gu==2048 ;
//                atomicAdd epilogue into out
//  [2368,6464) : experts token ; acquire g_done_r==64 ; inline routing
//                (thread 0) ; atomicAdd epilogue into out
// out pre-zeroed; each element gets EXACTLY two atomic adds -> deterministic.
// =====================================================================
__global__ __launch_bounds__(256, 2)
void mega_kernel(const u16* __restrict__ Xh, const u16* __restrict__ Xl,
                 const u16* __restrict__ Wgh, const u16* __restrict__ Wuh,
                 const u16* __restrict__ Wrh, const u16* __restrict__ Wrl,
                 u16* __restrict__ Hh, float* __restrict__ logits,
                 float* __restrict__ out,
                 const float* __restrict__ X,
                 const float* __restrict__ down_e,
                 const float* __restrict__ up_e)
{
    extern __shared__ char sm[];
    const int bidx = blockIdx.x;
    const int tid  = threadIdx.x;

    if (bidx < 2368) {
        const u32 sb = smem_u32(sm);
        const int lane = tid & 31;
        const int wid  = tid >> 5;
        const int l4 = lane & 15;
        const u32 aRowOff = (u32)((lane & 15) * PITCH + ((lane >> 4) << 4));
        const u32 bRowOff = (u32)((l4 & 7) * PITCH + ((l4 >> 3) << 4));

        if (bidx < 2048) {
            // ================= gate/up =================
            const int row0 = (bidx & 31) * 128;
            const int col0 = (bidx >> 5) * 64;
            const int warpM = (wid & 3) * 32;
            const int warpN = (wid >> 2) * 32;
            const int lrA = tid >> 1;
            const int cA  = (tid & 1) * 2;
            const int lrB = tid >> 2;
            const int cB  = tid & 3;
            const int NS = HID >> 5;

            auto load_stage = [&](int kt, int buf) {
                const u32 so = sb + buf * STG_GU;
                const size_t goA = (size_t)(row0 + lrA) * HID + kt * 32;
                cp16(so + lrA * PITCH + cA * 16,       Xh + goA + cA * 8);
                cp16(so + lrA * PITCH + (cA + 1) * 16, Xh + goA + (cA + 1) * 8);
                const size_t goB = (size_t)(col0 + lrB) * HID + kt * 32;
                cp16(so + PLANE128 + lrB * PITCH + cB * 16,           Wgh + goB + cB * 8);
                cp16(so + PLANE128 + PLANE64 + lrB * PITCH + cB * 16, Wuh + goB + cB * 8);
            };

            float accG[2][4][4], accU[2][4][4];
            #pragma unroll
            for (int i = 0; i < 2; i++)
                #pragma unroll
                for (int j = 0; j < 4; j++)
                    #pragma unroll
                    for (int t = 0; t < 4; t++) { accG[i][j][t] = 0.f; accU[i][j][t] = 0.f; }

            load_stage(0, 0); CP_COMMIT();
            load_stage(1, 1); CP_COMMIT();

            for (int s = 0; s < NS; s++) {
                const int buf = s % 3;
                CP_WAIT(1);
                __syncthreads();
                if (s + 2 < NS) load_stage(s + 2, (s + 2) % 3);
                CP_COMMIT();

                const u32 stg = sb + buf * STG_GU;
                #pragma unroll
                for (int ks = 0; ks < 2; ks++) {
                    const u32 kb = ks * 32;
                    u32 ah[2][4], bg[4][2], bu[4][2];
                    #pragma unroll
                    for (int i = 0; i < 2; i++)
                        ldsm_x4(ah[i][0], ah[i][1], ah[i][2], ah[i][3],
                                stg + (warpM + i * 16) * PITCH + kb + aRowOff);
                    #pragma unroll
                    for (int j = 0; j < 4; j++) {
                        const u32 rb = stg + PLANE128 + (warpN + j * 8) * PITCH + kb + bRowOff;
                        ldsm_x2(bg[j][0], bg[j][1], rb);
                        ldsm_x2(bu[j][0], bu[j][1], rb + PLANE64);
                    }
                    #pragma unroll
                    for (int i = 0; i < 2; i++)
                        #pragma unroll
                        for (int j = 0; j < 4; j++) {
                            mma_f32(accG[i][j], ah[i], bg[j]);
                            mma_f32(accU[i][j], ah[i], bu[j]);
                        }
                }
            }

            #pragma unroll
            for (int i = 0; i < 2; i++) {
                #pragma unroll
                for (int j = 0; j < 4; j++) {
                    const int r = row0 + warpM + i * 16 + (lane >> 2);
                    const int c = col0 + warpN + j * 8 + (lane & 3) * 2;
                    #pragma unroll
                    for (int half = 0; half < 2; half++) {
                        const int rr = r + half * 8;
                        const float gg0 = accG[i][j][half * 2 + 0];
                        const float gg1 = accG[i][j][half * 2 + 1];
                        const float uu0 = accU[i][j][half * 2 + 0];
                        const float uu1 = accU[i][j][half * 2 + 1];
                        __half2 hp = __halves2half2(__float2half_rn(silu(gg0) * uu0),
                                                    __float2half_rn(silu(gg1) * uu1));
                        ((u32*)Hh)[((size_t)rr * INTER + c) >> 1] = *(u32*)&hp;
                    }
                }
            }
            // release: H tile visible before count
            __threadfence();
            __syncthreads();
            if (tid == 0) atomicAdd(&g_done_gu, 1u);

        } else if (bidx < 2112) {
            // ================= router (fp16x3) =================
            const int rb_ = bidx - 2048;
            const int row0 = (rb_ & 31) * 128;
            const int col0 = (rb_ >> 5) * 64;
            const int warpM = (wid & 3) * 32;
            const int warpN = (wid >> 2) * 32;
            const int lrA = tid >> 1;
            const int cA  = (tid & 1) * 2;
            const int lrB = tid >> 2;
            const int cB  = tid & 3;
            const int NS = HID >> 5;

            auto load_stage = [&](int kt, int buf) {
                const u32 so = sb + buf * STG_R;
                const size_t goA = (size_t)(row0 + lrA) * HID + kt * 32;
                cp16(so + lrA * PITCH + cA * 16,                  Xh + goA + cA * 8);
                cp16(so + lrA * PITCH + (cA + 1) * 16,            Xh + goA + (cA + 1) * 8);
                cp16(so + PLANE128 + lrA * PITCH + cA * 16,       Xl + goA + cA * 8);
                cp16(so + PLANE128 + lrA * PITCH + (cA + 1) * 16, Xl + goA + (cA + 1) * 8);
                const size_t goB = (size_t)(col0 + lrB) * HID + kt * 32;
                cp16(so + 2 * PLANE128 + lrB * PITCH + cB * 16,           Wrh + goB + cB * 8);
                cp16(so + 2 * PLANE128 + PLANE64 + lrB * PITCH + cB * 16, Wrl + goB + cB * 8);
            };

            float acc[2][4][4];
            u32   accX[2][4][2];
            #pragma unroll
            for (int i = 0; i < 2; i++)
                #pragma unroll
                for (int j = 0; j < 4; j++) {
                    #pragma unroll
                    for (int t = 0; t < 4; t++) acc[i][j][t] = 0.f;
                    accX[i][j][0] = 0u; accX[i][j][1] = 0u;
                }

            load_stage(0, 0); CP_COMMIT();

            for (int s = 0; s < NS; s++) {
                const int buf = s & 1;
                if (s + 1 < NS) load_stage(s + 1, (s + 1) & 1);
                CP_COMMIT();
                CP_WAIT(1);
                __syncthreads();

                const u32 stg = sb + buf * STG_R;
                #pragma unroll
                for (int ks = 0; ks < 2; ks++) {
                    const u32 kb = ks * 32;
                    u32 ah[2][4], al[2][4], bh[4][2], bl[4][2];
                    #pragma unroll
                    for (int i = 0; i < 2; i++) {
                        const u32 ra = stg + (warpM + i * 16) * PITCH + kb + aRowOff;
                        ldsm_x4(ah[i][0], ah[i][1], ah[i][2], ah[i][3], ra);
                        ldsm_x4(al[i][0], al[i][1], al[i][2], al[i][3], ra + PLANE128);
                    }
                    #pragma unroll
                    for (int j = 0; j < 4; j++) {
                        const u32 rbq = stg + 2 * PLANE128 + (warpN + j * 8) * PITCH + kb + bRowOff;
                        ldsm_x2(bh[j][0], bh[j][1], rbq);
                        ldsm_x2(bl[j][0], bl[j][1], rbq + PLANE64);
                    }
                    #pragma unroll
                    for (int i = 0; i < 2; i++)
                        #pragma unroll
                        for (int j = 0; j < 4; j++) {
                            mma_f32(acc[i][j], ah[i], bh[j]);
                            mma_f16(accX[i][j], ah[i], bl[j]);
                            mma_f16(accX[i][j], al[i], bh[j]);
                        }
                }
                __syncthreads();
            }

            #pragma unroll
            for (int i = 0; i < 2; i++) {
                #pragma unroll
                for (int j = 0; j < 4; j++) {
                    float2 x0 = __half22float2(*(__half2*)&accX[i][j][0]);
                    float2 x1 = __half22float2(*(__half2*)&accX[i][j][1]);
                    const float vv[4] = { acc[i][j][0] + x0.x, acc[i][j][1] + x0.y,
                                          acc[i][j][2] + x1.x, acc[i][j][3] + x1.y };
                    const int r = row0 + warpM + i * 16 + (lane >> 2);
                    const int c = col0 + warpN + j * 8 + (lane & 3) * 2;
                    #pragma unroll
                    for (int half = 0; half < 2; half++) {
                        const int rr = r + half * 8;
                        *(float2*)(logits + (size_t)rr * 128 + c) =
                            make_float2(vv[half * 2 + 0], vv[half * 2 + 1]);
                    }
                }
            }
            __threadfence();
            __syncthreads();
            if (tid == 0) atomicAdd(&g_done_r, 1u);

        } else {
            // ================= down GEMM (acquire g_done_gu) =================
            if (tid == 0) {
                while (atomicAdd(&g_done_gu, 0u) < 2048u) { __nanosleep(128); }
            }
            __syncthreads();
            __threadfence();

            const int d = bidx - 2112;
            const int row0 = (d & 31) * 128;
            const int col0 = (d >> 5) * 128;
            const int warpM = (wid >> 2) * 64;
            const int warpN = (wid & 3) * 32;
            const int f  = tid * 2;
            const int lr = f >> 2;
            const int c0 = f & 3;
            const int NS = INTER >> 5;

            const u16* Bp = g_Wdh;
            auto load_stage2 = [&](int kt, int buf) {
                const size_t goA = (size_t)(row0 + lr) * INTER + kt * 32;
                const size_t goB = (size_t)(col0 + lr) * INTER + kt * 32;
                const u32 so = sb + buf * STG_GU + lr * PITCH;
                cp16(so + c0 * 16,                  Hh + goA + c0 * 8);
                cp16(so + (c0 + 1) * 16,            Hh + goA + (c0 + 1) * 8);
                cp16(so + PLANE128 + c0 * 16,       Bp + goB + c0 * 8);
                cp16(so + PLANE128 + (c0 + 1) * 16, Bp + goB + (c0 + 1) * 8);
            };

            float acc[4][4][4];
            #pragma unroll
            for (int i = 0; i < 4; i++)
                #pragma unroll
                for (int j = 0; j < 4; j++)
                    #pragma unroll
                    for (int t = 0; t < 4; t++) acc[i][j][t] = 0.f;

            load_stage2(0, 0); CP_COMMIT();
            load_stage2(1, 1); CP_COMMIT();

            for (int s = 0; s < NS; s++) {
                const int buf = s % 3;
                CP_WAIT(1);
                __syncthreads();
                if (s + 2 < NS) load_stage2(s + 2, (s + 2) % 3);
                CP_COMMIT();

                const u32 stg = sb + buf * STG_GU;
                #pragma unroll
                for (int ks = 0; ks < 2; ks++) {
                    const u32 kb = ks * 32;
                    u32 ah[4][4], bh[4][2];
                    #pragma unroll
                    for (int i = 0; i < 4; i++)
                        ldsm_x4(ah[i][0], ah[i][1], ah[i][2], ah[i][3],
                                stg + (warpM + i * 16) * PITCH + kb + aRowOff);
                    #pragma unroll
                    for (int j = 0; j < 4; j++)
                        ldsm_x2(bh[j][0], bh[j][1],
                                stg + PLANE128 + (warpN + j * 8) * PITCH + kb + bRowOff);
                    #pragma unroll
                    for (int i = 0; i < 4; i++)
                        #pragma unroll
                        for (int j = 0; j < 4; j++) mma_f32(acc[i][j], ah[i], bh[j]);
                }
            }

            #pragma unroll
            for (int i = 0; i < 4; i++) {
                #pragma unroll
                for (int j = 0; j < 4; j++) {
                    const int r = row0 + warpM + i * 16 + (lane >> 2);
                    const int c = col0 + warpN + j * 8 + (lane & 3) * 2;
                    #pragma unroll
                    for (int half = 0; half < 2; half++) {
                        const int rr = r + half * 8;
                        atomicAdd(out + (size_t)rr * HID + c,     acc[i][j][half * 2 + 0]);
                        atomicAdd(out + (size_t)rr * HID + c + 1, acc[i][j][half * 2 + 1]);
                    }
                }
            }
        }
    } else {
        // ================= experts (acquire g_done_r, inline routing) =================
        const int m = bidx - 2368;
        float4* xs4  = (float4*)sm;
        float*  ews  = (float*)(sm + 4096);
        int*    sidx = (int*)(sm + 4096 + 64);
        float*  swt  = (float*)(sm + 4096 + 128);

        if (tid == 0) {
            while (atomicAdd(&g_done_r, 0u) < 64u) { __nanosleep(128); }
        }
        __syncthreads();
        __threadfence();

        xs4[tid] = ((const float4*)(X + (size_t)m * HID))[tid];

        if (tid == 0) {
            const float* px = logits + (size_t)(m >> 1) * 128 + (m & 1) * 64;
            const float* py = logits + (size_t)(2048 + (m >> 1)) * 128 + (m & 1) * 64;
            float vx[8], vy[8];
            int   ix[8], iy[8];
            #pragma unroll
            for (int t = 0; t < 8; t++) { vx[t] = -3.4e38f; vy[t] = -3.4e38f; ix[t] = 0; iy[t] = 0; }
            for (int k = 0; k < NKEYS; k++) top8_insert(px[k], k, vx, ix);
            for (int k = 0; k < NKEYS; k++) top8_insert(py[k], k, vy, iy);
            float sv[8]; int sa[8];
            #pragma unroll
            for (int t = 0; t < 8; t++) { sv[t] = -3.4e38f; sa[t] = 0; }
            for (int a = 0; a < 8; a++)
                for (int bq = 0; bq < 8; bq++)
                    top8_insert(vx[a] + vy[bq], a * 8 + bq, sv, sa);
            float mx = sv[0];
            float e[8], s = 0.f;
            #pragma unroll
            for (int t = 0; t < 8; t++) { e[t] = expf(sv[t] - mx); s += e[t]; }
            float w[8], s2 = 0.f;
            #pragma unroll
            for (int t = 0; t < 8; t++) { w[t] = e[t] / s; s2 += w[t]; }
            #pragma unroll
            for (int t = 0; t < 8; t++) {
                int a = sa[t] >> 3, bq = sa[t] & 7;
                sidx[t] = ix[a] * NKEYS + iy[bq];
                swt[t]  = w[t] / s2;
            }
        }
        __syncthreads();

        const float* xs = (const float*)xs4;
        const int wid  = tid >> 5;
        const int lane = tid & 31;

        {
            int e = sidx[wid];
            const float* dd = down_e + (size_t)e * HID;
            float s = 0.f;
            for (int k = lane; k < HID; k += 32) s = fmaf(dd[k], xs[k], s);
            #pragma unroll
            for (int o = 16; o; o >>= 1) s += __shfl_xor_sync(0xffffffffu, s, o);
            if (lane == 0) {
                float sig = s / (1.f + expf(-s));
                ews[wid] = sig * swt[wid];
            }
        }
        __syncthreads();

        float4 acc = make_float4(0.f, 0.f, 0.f, 0.f);
        #pragma unroll
        for (int k = 0; k < TOPK; k++) {
            int e = sidx[k];
            float w = ews[k];
            float4 u = ((const float4*)(up_e + (size_t)e * HID))[tid];
            acc.x = fmaf(w, u.x, acc.x);
            acc.y = fmaf(w, u.y, acc.y);
            acc.z = fmaf(w, u.z, acc.z);
            acc.w = fmaf(w, u.w, acc.w);
        }
        float* dst = out + (size_t)m * HID + tid * 4;
        atomicAdd(dst + 0, acc.x);
        atomicAdd(dst + 1, acc.y);
        atomicAdd(dst + 2, acc.z);
        atomicAdd(dst + 3, acc.w);
    }
}

// ---------------- launch ----------------
static void* sym(const void* s) { void* p = nullptr; cudaGetSymbolAddress(&p, s); return p; }

extern "C" void kernel_launch(void* const* d_in, const int* in_sizes, int n_in,
                              void* d_out, int out_size)
{
    const float* X        = (const float*)d_in[0];
    const float* w_gate   = (const float*)d_in[1];
    const float* w_up     = (const float*)d_in[2];
    const float* w_down   = (const float*)d_in[3];
    const float* w_router = (const float*)d_in[4];
    const float* down_e   = (const float*)d_in[5];
    const float* up_e     = (const float*)d_in[6];

    float* out    = (float*)d_out;
    float* logits = (float*)d_out + (size_t)NTOK * HID;

    u16 *Xh = (u16*)sym(g_Xh),  *Xl = (u16*)sym(g_Xl);
    u16 *Wgh = (u16*)sym(g_Wgh);
    u16 *Wuh = (u16*)sym(g_Wuh);
    u16 *Wdh = (u16*)sym(g_Wdh);
    u16 *Wrh = (u16*)sym(g_Wrh), *Wrl = (u16*)sym(g_Wrl);
    u16 *Hh = (u16*)sym(g_Hh);

    cudaFuncSetAttribute(mega_kernel, cudaFuncAttributeMaxDynamicSharedMemorySize, SMEM_MEGA);

    // 0) all splits + zero out + counter reset, one launch
    split_all_kernel<<<20608, 256>>>(X, w_router, w_gate, w_up, w_down,
                                     Xh, Xl, Wrh, Wrl, Wgh, Wuh, Wdh, out);
    // 1) everything else: gate/up + router + down + experts with intra-kernel dataflow
    mega_kernel<<<6464, 256, SMEM_MEGA>>>(Xh, Xl, Wgh, Wuh, Wrh, Wrl,
                                          Hh, logits, out, X, down_e, up_e);
    (void)in_sizes; (void)n_in; (void)out_size;
}

// round 15
// speedup vs baseline: 1.4519x; 1.4519x over previous
#include <cuda_runtime.h>
#include <cuda_fp16.h>
#include <cstdint>
#include <math.h>

#define HID    1024
#define INTER  4096
#define NTOK   4096
#define NKEYS  64
#define TOPK   8

typedef unsigned short u16;
typedef unsigned int   u32;

// ---------------- scratch (no allocations allowed) ----------------
__device__ __align__(16) static u16   g_Xh[(size_t)NTOK * HID];
__device__ __align__(16) static u16   g_Xl[(size_t)NTOK * HID];
__device__ __align__(16) static u16   g_Wgh[(size_t)INTER * HID];
__device__ __align__(16) static u16   g_Wuh[(size_t)INTER * HID];
__device__ __align__(16) static u16   g_Wdh[(size_t)HID * INTER];
__device__ __align__(16) static u16   g_Wrh[(size_t)128 * HID];
__device__ __align__(16) static u16   g_Wrl[(size_t)128 * HID];
__device__ __align__(16) static u16   g_Hh[(size_t)NTOK * INTER];
__device__ static int   g_tidx[NTOK * TOPK];
__device__ static float g_tw[NTOK * TOPK];

// ---------------- helpers ----------------
__device__ __forceinline__ u32 smem_u32(const void* p) {
    u32 a;
    asm("{ .reg .u64 t; cvta.to.shared.u64 t, %1; cvt.u32.u64 %0, t; }" : "=r"(a) : "l"(p));
    return a;
}

__device__ __forceinline__ void cp16(u32 dst, const void* src) {
    asm volatile("cp.async.cg.shared.global [%0], [%1], 16;" :: "r"(dst), "l"(src));
}
#define CP_COMMIT() asm volatile("cp.async.commit_group;" ::: "memory")
#define CP_WAIT(n)  asm volatile("cp.async.wait_group %0;" :: "n"(n) : "memory")

__device__ __forceinline__ void ldsm_x4(u32& r0, u32& r1, u32& r2, u32& r3, u32 addr) {
    asm volatile("ldmatrix.sync.aligned.m8n8.x4.shared.b16 {%0,%1,%2,%3}, [%4];"
                 : "=r"(r0), "=r"(r1), "=r"(r2), "=r"(r3) : "r"(addr));
}
__device__ __forceinline__ void ldsm_x2(u32& r0, u32& r1, u32 addr) {
    asm volatile("ldmatrix.sync.aligned.m8n8.x2.shared.b16 {%0,%1}, [%2];"
                 : "=r"(r0), "=r"(r1) : "r"(addr));
}

__device__ __forceinline__ void mma_f32(float* c, const u32* a, const u32* b) {
    asm volatile(
        "mma.sync.aligned.m16n8k16.row.col.f32.f16.f16.f32 "
        "{%0,%1,%2,%3}, {%4,%5,%6,%7}, {%8,%9}, {%0,%1,%2,%3};"
        : "+f"(c[0]), "+f"(c[1]), "+f"(c[2]), "+f"(c[3])
        : "r"(a[0]), "r"(a[1]), "r"(a[2]), "r"(a[3]), "r"(b[0]), "r"(b[1]));
}
__device__ __forceinline__ void mma_f16(u32* c, const u32* a, const u32* b) {
    asm volatile(
        "mma.sync.aligned.m16n8k16.row.col.f16.f16.f16.f16 "
        "{%0,%1}, {%2,%3,%4,%5}, {%6,%7}, {%0,%1};"
        : "+r"(c[0]), "+r"(c[1])
        : "r"(a[0]), "r"(a[1]), "r"(a[2]), "r"(a[3]), "r"(b[0]), "r"(b[1]));
}

__device__ __forceinline__ float silu(float x) { return x / (1.f + expf(-x)); }

// =====================================================================
// split_all_kernel: all fp32->fp16 conversions, one launch, grid 4128.
// Coarsened: each thread converts 4 float4 (MLP 4) -> ~2x BW vs R8.
// blocks [0,1024): X split2 ; [1024,1056): Wr split2 ;
// [1056,2080): Wg ; [2080,3104): Wu ; [3104,4128): Wd (split1)
// =====================================================================
__global__ void split_all_kernel(const float* __restrict__ X,
                                 const float* __restrict__ Wr,
                                 const float* __restrict__ Wg,
                                 const float* __restrict__ Wu,
                                 const float* __restrict__ Wd,
                                 u16* __restrict__ Xh, u16* __restrict__ Xl,
                                 u16* __restrict__ Wrh, u16* __restrict__ Wrl,
                                 u16* __restrict__ Wgh, u16* __restrict__ Wuh,
                                 u16* __restrict__ Wdh)
{
    const int b = blockIdx.x;
    const int tid = threadIdx.x;
    if (b < 1056) {
        // -------- split2 path (X, Wr) --------
        const float* src; u16 *hi, *lo; int base;
        if (b < 1024) { src = X;  hi = Xh;  lo = Xl;  base = b * 1024; }
        else          { src = Wr; hi = Wrh; lo = Wrl; base = (b - 1024) * 1024; }
        #pragma unroll
        for (int k = 0; k < 4; k++) {
            const int i = base + k * 256 + tid;
            float4 v = ((const float4*)src)[i];
            __half hx = __float2half_rn(v.x), hy = __float2half_rn(v.y);
            __half hz = __float2half_rn(v.z), hw = __float2half_rn(v.w);
            __half lx = __float2half_rn(v.x - __half2float(hx));
            __half ly = __float2half_rn(v.y - __half2float(hy));
            __half lz = __float2half_rn(v.z - __half2float(hz));
            __half lw = __float2half_rn(v.w - __half2float(hw));
            __half2 h0 = __halves2half2(hx, hy), h1 = __halves2half2(hz, hw);
            __half2 l0 = __halves2half2(lx, ly), l1 = __halves2half2(lz, lw);
            ((uint2*)hi)[i] = make_uint2(*(u32*)&h0, *(u32*)&h1);
            ((uint2*)lo)[i] = make_uint2(*(u32*)&l0, *(u32*)&l1);
        }
    } else {
        // -------- split1 path (Wg, Wu, Wd) --------
        const float* src; u16* dst; int base;
        if (b < 2080)      { src = Wg; dst = Wgh; base = (b - 1056) * 1024; }
        else if (b < 3104) { src = Wu; dst = Wuh; base = (b - 2080) * 1024; }
        else               { src = Wd; dst = Wdh; base = (b - 3104) * 1024; }
        #pragma unroll
        for (int k = 0; k < 4; k++) {
            const int i = base + k * 256 + tid;
            float4 v = ((const float4*)src)[i];
            __half2 h0 = __halves2half2(__float2half_rn(v.x), __float2half_rn(v.y));
            __half2 h1 = __halves2half2(__float2half_rn(v.z), __float2half_rn(v.w));
            ((uint2*)dst)[i] = make_uint2(*(u32*)&h0, *(u32*)&h1);
        }
    }
}

#define PITCH 80
#define PLANE128 10240                // 128 rows * 80
#define PLANE64  5120                 // 64 rows * 80

// =====================================================================
// mlp1_kernel (R8-proven): grid (32, 66), 256 thr, occ 2.
//  y < 64 : fused gate/up — Hh = f16(silu(X@Wg^T) * (X@Wu^T))
//  y >= 64: router (fp16x3) — logits columns [(y-64)*64 .. +64)
// CTA tile 128(M)x64(N), BK=32.
// =====================================================================
#define STG_GU 20480
#define STG_R  30720
#define SMEM_MLP1 61440

__global__ __launch_bounds__(256, 2)
void mlp1_kernel(const u16* __restrict__ Xh, const u16* __restrict__ Xl,
                 const u16* __restrict__ Wgh, const u16* __restrict__ Wuh,
                 const u16* __restrict__ Wrh, const u16* __restrict__ Wrl,
                 u16* __restrict__ Hh, float* __restrict__ logits)
{
    extern __shared__ char sm[];
    const u32 sb = smem_u32(sm);
    const int tid  = threadIdx.x;
    const int lane = tid & 31;
    const int wid  = tid >> 5;
    const int row0 = blockIdx.x * 128;
    const int warpM = (wid & 3) * 32;
    const int warpN = (wid >> 2) * 32;

    const int lrA = tid >> 1;
    const int cA  = (tid & 1) * 2;
    const int lrB = tid >> 2;
    const int cB  = tid & 3;

    const int l4 = lane & 15;
    const u32 aRowOff = (u32)((lane & 15) * PITCH + ((lane >> 4) << 4));
    const u32 bRowOff = (u32)((l4 & 7) * PITCH + ((l4 >> 3) << 4));

    const int NS = HID >> 5;

    if (blockIdx.y < 64) {
        const int col0 = blockIdx.y * 64;

        auto load_stage = [&](int kt, int buf) {
            const u32 so = sb + buf * STG_GU;
            const size_t goA = (size_t)(row0 + lrA) * HID + kt * 32;
            cp16(so + lrA * PITCH + cA * 16,       Xh + goA + cA * 8);
            cp16(so + lrA * PITCH + (cA + 1) * 16, Xh + goA + (cA + 1) * 8);
            const size_t goB = (size_t)(col0 + lrB) * HID + kt * 32;
            cp16(so + PLANE128 + lrB * PITCH + cB * 16,            Wgh + goB + cB * 8);
            cp16(so + PLANE128 + PLANE64 + lrB * PITCH + cB * 16,  Wuh + goB + cB * 8);
        };

        float accG[2][4][4], accU[2][4][4];
        #pragma unroll
        for (int i = 0; i < 2; i++)
            #pragma unroll
            for (int j = 0; j < 4; j++)
                #pragma unroll
                for (int t = 0; t < 4; t++) { accG[i][j][t] = 0.f; accU[i][j][t] = 0.f; }

        load_stage(0, 0); CP_COMMIT();
        load_stage(1, 1); CP_COMMIT();

        for (int s = 0; s < NS; s++) {
            const int buf = s % 3;
            CP_WAIT(1);
            __syncthreads();
            if (s + 2 < NS) load_stage(s + 2, (s + 2) % 3);
            CP_COMMIT();

            const u32 stg = sb + buf * STG_GU;
            #pragma unroll
            for (int ks = 0; ks < 2; ks++) {
                const u32 kb = ks * 32;
                u32 ah[2][4], bg[4][2], bu[4][2];
                #pragma unroll
                for (int i = 0; i < 2; i++)
                    ldsm_x4(ah[i][0], ah[i][1], ah[i][2], ah[i][3],
                            stg + (warpM + i * 16) * PITCH + kb + aRowOff);
                #pragma unroll
                for (int j = 0; j < 4; j++) {
                    const u32 rb = stg + PLANE128 + (warpN + j * 8) * PITCH + kb + bRowOff;
                    ldsm_x2(bg[j][0], bg[j][1], rb);
                    ldsm_x2(bu[j][0], bu[j][1], rb + PLANE64);
                }
                #pragma unroll
                for (int i = 0; i < 2; i++)
                    #pragma unroll
                    for (int j = 0; j < 4; j++) {
                        mma_f32(accG[i][j], ah[i], bg[j]);
                        mma_f32(accU[i][j], ah[i], bu[j]);
                    }
            }
        }

        #pragma unroll
        for (int i = 0; i < 2; i++) {
            #pragma unroll
            for (int j = 0; j < 4; j++) {
                const int r = row0 + warpM + i * 16 + (lane >> 2);
                const int c = col0 + warpN + j * 8 + (lane & 3) * 2;
                #pragma unroll
                for (int half = 0; half < 2; half++) {
                    const int rr = r + half * 8;
                    const float gg0 = accG[i][j][half * 2 + 0];
                    const float gg1 = accG[i][j][half * 2 + 1];
                    const float uu0 = accU[i][j][half * 2 + 0];
                    const float uu1 = accU[i][j][half * 2 + 1];
                    __half2 hp = __halves2half2(__float2half_rn(silu(gg0) * uu0),
                                                __float2half_rn(silu(gg1) * uu1));
                    ((u32*)Hh)[((size_t)rr * INTER + c) >> 1] = *(u32*)&hp;
                }
            }
        }
    } else {
        const int col0 = (blockIdx.y - 64) * 64;

        auto load_stage = [&](int kt, int buf) {
            const u32 so = sb + buf * STG_R;
            const size_t goA = (size_t)(row0 + lrA) * HID + kt * 32;
            cp16(so + lrA * PITCH + cA * 16,                  Xh + goA + cA * 8);
            cp16(so + lrA * PITCH + (cA + 1) * 16,            Xh + goA + (cA + 1) * 8);
            cp16(so + PLANE128 + lrA * PITCH + cA * 16,       Xl + goA + cA * 8);
            cp16(so + PLANE128 + lrA * PITCH + (cA + 1) * 16, Xl + goA + (cA + 1) * 8);
            const size_t goB = (size_t)(col0 + lrB) * HID + kt * 32;
            cp16(so + 2 * PLANE128 + lrB * PITCH + cB * 16,           Wrh + goB + cB * 8);
            cp16(so + 2 * PLANE128 + PLANE64 + lrB * PITCH + cB * 16, Wrl + goB + cB * 8);
        };

        float acc[2][4][4];
        u32   accX[2][4][2];
        #pragma unroll
        for (int i = 0; i < 2; i++)
            #pragma unroll
            for (int j = 0; j < 4; j++) {
                #pragma unroll
                for (int t = 0; t < 4; t++) acc[i][j][t] = 0.f;
                accX[i][j][0] = 0u; accX[i][j][1] = 0u;
            }

        load_stage(0, 0); CP_COMMIT();

        for (int s = 0; s < NS; s++) {
            const int buf = s & 1;
            if (s + 1 < NS) load_stage(s + 1, (s + 1) & 1);
            CP_COMMIT();
            CP_WAIT(1);
            __syncthreads();

            const u32 stg = sb + buf * STG_R;
            #pragma unroll
            for (int ks = 0; ks < 2; ks++) {
                const u32 kb = ks * 32;
                u32 ah[2][4], al[2][4], bh[4][2], bl[4][2];
                #pragma unroll
                for (int i = 0; i < 2; i++) {
                    const u32 ra = stg + (warpM + i * 16) * PITCH + kb + aRowOff;
                    ldsm_x4(ah[i][0], ah[i][1], ah[i][2], ah[i][3], ra);
                    ldsm_x4(al[i][0], al[i][1], al[i][2], al[i][3], ra + PLANE128);
                }
                #pragma unroll
                for (int j = 0; j < 4; j++) {
                    const u32 rb = stg + 2 * PLANE128 + (warpN + j * 8) * PITCH + kb + bRowOff;
                    ldsm_x2(bh[j][0], bh[j][1], rb);
                    ldsm_x2(bl[j][0], bl[j][1], rb + PLANE64);
                }
                #pragma unroll
                for (int i = 0; i < 2; i++)
                    #pragma unroll
                    for (int j = 0; j < 4; j++) {
                        mma_f32(acc[i][j], ah[i], bh[j]);
                        mma_f16(accX[i][j], ah[i], bl[j]);
                        mma_f16(accX[i][j], al[i], bh[j]);
                    }
            }
            __syncthreads();
        }

        #pragma unroll
        for (int i = 0; i < 2; i++) {
            #pragma unroll
            for (int j = 0; j < 4; j++) {
                float2 x0 = __half22float2(*(__half2*)&accX[i][j][0]);
                float2 x1 = __half22float2(*(__half2*)&accX[i][j][1]);
                const float vv[4] = { acc[i][j][0] + x0.x, acc[i][j][1] + x0.y,
                                      acc[i][j][2] + x1.x, acc[i][j][3] + x1.y };
                const int r = row0 + warpM + i * 16 + (lane >> 2);
                const int c = col0 + warpN + j * 8 + (lane & 3) * 2;
                #pragma unroll
                for (int half = 0; half < 2; half++) {
                    const int rr = r + half * 8;
                    *(float2*)(logits + (size_t)rr * 128 + c) =
                        make_float2(vv[half * 2 + 0], vv[half * 2 + 1]);
                }
            }
        }
    }
}

// =====================================================================
// routing_zero_kernel (R8-proven): grid 4096. Every block zeros its 4KB
// slice of out; blocks [0,16) also compute routing.
// =====================================================================
__device__ __forceinline__ void top8_insert(float v, int idx, float* hv, int* hi) {
    if (v <= hv[7]) return;
    int p = 7;
    #pragma unroll
    for (int q = 7; q > 0; q--) {
        if (v > hv[q-1]) { hv[q] = hv[q-1]; hi[q] = hi[q-1]; p = q - 1; }
    }
    hv[p] = v; hi[p] = idx;
}

__global__ void routing_zero_kernel(const float* __restrict__ logits,
                                    float* __restrict__ out)
{
    const int b = blockIdx.x;
    const int tid = threadIdx.x;
    ((float4*)out)[b * 256 + tid] = make_float4(0.f, 0.f, 0.f, 0.f);
    if (b >= 16) return;

    const int m = b * 256 + tid;
    const float* px = logits + (size_t)(m >> 1) * 128 + (m & 1) * 64;
    const float* py = logits + (size_t)(2048 + (m >> 1)) * 128 + (m & 1) * 64;

    float vx[8], vy[8];
    int   ix[8], iy[8];
    #pragma unroll
    for (int t = 0; t < 8; t++) { vx[t] = -3.4e38f; vy[t] = -3.4e38f; ix[t] = 0; iy[t] = 0; }
    for (int k = 0; k < NKEYS; k++) top8_insert(px[k], k, vx, ix);
    for (int k = 0; k < NKEYS; k++) top8_insert(py[k], k, vy, iy);

    float sv[8]; int sa[8];
    #pragma unroll
    for (int t = 0; t < 8; t++) { sv[t] = -3.4e38f; sa[t] = 0; }
    for (int a = 0; a < 8; a++)
        for (int bq = 0; bq < 8; bq++)
            top8_insert(vx[a] + vy[bq], a * 8 + bq, sv, sa);

    float mx = sv[0];
    float e[8], s = 0.f;
    #pragma unroll
    for (int t = 0; t < 8; t++) { e[t] = expf(sv[t] - mx); s += e[t]; }
    float w[8], s2 = 0.f;
    #pragma unroll
    for (int t = 0; t < 8; t++) { w[t] = e[t] / s; s2 += w[t]; }
    #pragma unroll
    for (int t = 0; t < 8; t++) w[t] /= s2;

    #pragma unroll
    for (int t = 0; t < 8; t++) {
        int a = sa[t] >> 3, bq = sa[t] & 7;
        g_tidx[m * TOPK + t] = ix[a] * NKEYS + iy[bq];
        g_tw[m * TOPK + t]   = w[t];
    }
}

// =====================================================================
// tail_kernel (R8-proven): grid 256 + 4096, occ 2.
//  bid < 256 : down GEMM tile (128x128, 4-stage, atomicAdd epilogue)
//  bid >= 256: experts token (atomicAdd epilogue), backfills idle slots.
// out pre-zeroed; each element gets EXACTLY two atomic adds -> deterministic.
// =====================================================================
#define STG1 20480                    // 2 x PLANE128
#define SMEM_TAIL (4 * STG1)          // 81920

__global__ __launch_bounds__(256, 2)
void tail_kernel(const u16* __restrict__ A_h, const u16* __restrict__ B_h,
                 float* __restrict__ out,
                 const float* __restrict__ X,
                 const float* __restrict__ down_e,
                 const float* __restrict__ up_e)
{
    extern __shared__ char sm[];
    const int tid  = threadIdx.x;

    if (blockIdx.x < 256) {
        const u32 sb = smem_u32(sm);
        const int lane = tid & 31;
        const int wid  = tid >> 5;
        const int row0 = (blockIdx.x & 31) * 128;
        const int col0 = (blockIdx.x >> 5) * 128;
        const int warpM = (wid >> 2) * 64;
        const int warpN = (wid & 3) * 32;
        const int K = INTER, ldC = HID;

        const int f  = tid * 2;
        const int lr = f >> 2;
        const int c0 = f & 3;

        const int NS = K >> 5;

        auto load_stage = [&](int kt, int buf) {
            const size_t goA = (size_t)(row0 + lr) * K + kt * 32;
            const size_t goB = (size_t)(col0 + lr) * K + kt * 32;
            const u32 so = sb + buf * STG1 + lr * PITCH;
            cp16(so + c0 * 16,                  A_h + goA + c0 * 8);
            cp16(so + (c0 + 1) * 16,            A_h + goA + (c0 + 1) * 8);
            cp16(so + PLANE128 + c0 * 16,       B_h + goB + c0 * 8);
            cp16(so + PLANE128 + (c0 + 1) * 16, B_h + goB + (c0 + 1) * 8);
        };

        float acc[4][4][4];
        #pragma unroll
        for (int i = 0; i < 4; i++)
            #pragma unroll
            for (int j = 0; j < 4; j++)
                #pragma unroll
                for (int t = 0; t < 4; t++) acc[i][j][t] = 0.f;

        const int l4 = lane & 15;
        const u32 aRowOff = (u32)((lane & 15) * PITCH + ((lane >> 4) << 4));
        const u32 bRowOff = (u32)((l4 & 7) * PITCH + ((l4 >> 3) << 4));

        load_stage(0, 0); CP_COMMIT();
        load_stage(1, 1); CP_COMMIT();
        load_stage(2, 2); CP_COMMIT();

        for (int s = 0; s < NS; s++) {
            const int buf = s & 3;
            CP_WAIT(2);
            __syncthreads();
            if (s + 3 < NS) load_stage(s + 3, (s + 3) & 3);
            CP_COMMIT();

            const u32 stg = sb + buf * STG1;
            #pragma unroll
            for (int ks = 0; ks < 2; ks++) {
                const u32 kb = ks * 32;
                u32 ah[4][4], bh[4][2];
                #pragma unroll
                for (int i = 0; i < 4; i++)
                    ldsm_x4(ah[i][0], ah[i][1], ah[i][2], ah[i][3],
                            stg + (warpM + i * 16) * PITCH + kb + aRowOff);
                #pragma unroll
                for (int j = 0; j < 4; j++)
                    ldsm_x2(bh[j][0], bh[j][1],
                            stg + PLANE128 + (warpN + j * 8) * PITCH + kb + bRowOff);
                #pragma unroll
                for (int i = 0; i < 4; i++)
                    #pragma unroll
                    for (int j = 0; j < 4; j++) mma_f32(acc[i][j], ah[i], bh[j]);
            }
        }

        #pragma unroll
        for (int i = 0; i < 4; i++) {
            #pragma unroll
            for (int j = 0; j < 4; j++) {
                const int r = row0 + warpM + i * 16 + (lane >> 2);
                const int c = col0 + warpN + j * 8 + (lane & 3) * 2;
                #pragma unroll
                for (int half = 0; half < 2; half++) {
                    const int rr = r + half * 8;
                    atomicAdd(out + (size_t)rr * ldC + c,     acc[i][j][half * 2 + 0]);
                    atomicAdd(out + (size_t)rr * ldC + c + 1, acc[i][j][half * 2 + 1]);
                }
            }
        }
    } else {
        const int m = blockIdx.x - 256;
        float4* xs4 = (float4*)sm;
        float*  ews = (float*)(sm + 4096);

        xs4[tid] = ((const float4*)(X + (size_t)m * HID))[tid];
        __syncthreads();

        const float* xs = (const float*)xs4;
        const int wid  = tid >> 5;
        const int lane = tid & 31;

        {
            int e = g_tidx[m * TOPK + wid];
            const float* d = down_e + (size_t)e * HID;
            float s = 0.f;
            for (int k = lane; k < HID; k += 32) s = fmaf(d[k], xs[k], s);
            #pragma unroll
            for (int o = 16; o; o >>= 1) s += __shfl_xor_sync(0xffffffffu, s, o);
            if (lane == 0) {
                float sig = s / (1.f + expf(-s));
                ews[wid] = sig * g_tw[m * TOPK + wid];
            }
        }
        __syncthreads();

        float4 acc = make_float4(0.f, 0.f, 0.f, 0.f);
        #pragma unroll
        for (int k = 0; k < TOPK; k++) {
            int e = g_tidx[m * TOPK + k];
            float w = ews[k];
            float4 u = ((const float4*)(up_e + (size_t)e * HID))[tid];
            acc.x = fmaf(w, u.x, acc.x);
            acc.y = fmaf(w, u.y, acc.y);
            acc.z = fmaf(w, u.z, acc.z);
            acc.w = fmaf(w, u.w, acc.w);
        }
        float* dst = out + (size_t)m * HID + tid * 4;
        atomicAdd(dst + 0, acc.x);
        atomicAdd(dst + 1, acc.y);
        atomicAdd(dst + 2, acc.z);
        atomicAdd(dst + 3, acc.w);
    }
}

// ---------------- launch ----------------
static void* sym(const void* s) { void* p = nullptr; cudaGetSymbolAddress(&p, s); return p; }

extern "C" void kernel_launch(void* const* d_in, const int* in_sizes, int n_in,
                              void* d_out, int out_size)
{
    const float* X        = (const float*)d_in[0];
    const float* w_gate   = (const float*)d_in[1];
    const float* w_up     = (const float*)d_in[2];
    const float* w_down   = (const float*)d_in[3];
    const float* w_router = (const float*)d_in[4];
    const float* down_e   = (const float*)d_in[5];
    const float* up_e     = (const float*)d_in[6];

    float* out    = (float*)d_out;
    float* logits = (float*)d_out + (size_t)NTOK * HID;

    u16 *Xh = (u16*)sym(g_Xh),  *Xl = (u16*)sym(g_Xl);
    u16 *Wgh = (u16*)sym(g_Wgh);
    u16 *Wuh = (u16*)sym(g_Wuh);
    u16 *Wdh = (u16*)sym(g_Wdh);
    u16 *Wrh = (u16*)sym(g_Wrh), *Wrl = (u16*)sym(g_Wrl);
    u16 *Hh = (u16*)sym(g_Hh);

    cudaFuncSetAttribute(mlp1_kernel, cudaFuncAttributeMaxDynamicSharedMemorySize, SMEM_MLP1);
    cudaFuncSetAttribute(tail_kernel, cudaFuncAttributeMaxDynamicSharedMemorySize, SMEM_TAIL);

    // 0) all splits, one coarse launch (MLP 4 per thread)
    split_all_kernel<<<4128, 256>>>(X, w_router, w_gate, w_up, w_down,
                                    Xh, Xl, Wrh, Wrl, Wgh, Wuh, Wdh);
    // 1) fused gate/up + router
    mlp1_kernel<<<dim3(NTOK / 128, 66), 256, SMEM_MLP1>>>(
        Xh, Xl, Wgh, Wuh, Wrh, Wrl, Hh, logits);
    // 2) routing top-k + zero out
    routing_zero_kernel<<<4096, 256>>>(logits, out);
    // 3) down GEMM + experts (R8-proven tail)
    tail_kernel<<<256 + NTOK, 256, SMEM_TAIL>>>(Hh, Wdh, out, X, down_e, up_e);
    (void)in_sizes; (void)n_in; (void)out_size;
}

// round 16
// speedup vs baseline: 1.5006x; 1.0336x over previous
#include <cuda_runtime.h>
#include <cuda_fp16.h>
#include <cstdint>
#include <math.h>

#define HID    1024
#define INTER  4096
#define NTOK   4096
#define NKEYS  64
#define TOPK   8

typedef unsigned short u16;
typedef unsigned int   u32;

// ---------------- scratch (no allocations allowed) ----------------
__device__ __align__(16) static u16   g_Xh[(size_t)NTOK * HID];
__device__ __align__(16) static u16   g_Xl[(size_t)NTOK * HID];
__device__ __align__(16) static u16   g_Wgh[(size_t)INTER * HID];
__device__ __align__(16) static u16   g_Wuh[(size_t)INTER * HID];
__device__ __align__(16) static u16   g_Wdh[(size_t)HID * INTER];
__device__ __align__(16) static u16   g_Wrh[(size_t)128 * HID];
__device__ __align__(16) static u16   g_Wrl[(size_t)128 * HID];
__device__ __align__(16) static u16   g_Hh[(size_t)NTOK * INTER];
__device__ static int   g_tidx[NTOK * TOPK];
__device__ static float g_tw[NTOK * TOPK];
__device__ static u32   g_done_rt;

// ---------------- helpers ----------------
__device__ __forceinline__ u32 smem_u32(const void* p) {
    u32 a;
    asm("{ .reg .u64 t; cvta.to.shared.u64 t, %1; cvt.u32.u64 %0, t; }" : "=r"(a) : "l"(p));
    return a;
}

__device__ __forceinline__ void cp16(u32 dst, const void* src) {
    asm volatile("cp.async.cg.shared.global [%0], [%1], 16;" :: "r"(dst), "l"(src));
}
#define CP_COMMIT() asm volatile("cp.async.commit_group;" ::: "memory")
#define CP_WAIT(n)  asm volatile("cp.async.wait_group %0;" :: "n"(n) : "memory")

__device__ __forceinline__ void ldsm_x4(u32& r0, u32& r1, u32& r2, u32& r3, u32 addr) {
    asm volatile("ldmatrix.sync.aligned.m8n8.x4.shared.b16 {%0,%1,%2,%3}, [%4];"
                 : "=r"(r0), "=r"(r1), "=r"(r2), "=r"(r3) : "r"(addr));
}
__device__ __forceinline__ void ldsm_x2(u32& r0, u32& r1, u32 addr) {
    asm volatile("ldmatrix.sync.aligned.m8n8.x2.shared.b16 {%0,%1}, [%2];"
                 : "=r"(r0), "=r"(r1) : "r"(addr));
}

__device__ __forceinline__ void mma_f32(float* c, const u32* a, const u32* b) {
    asm volatile(
        "mma.sync.aligned.m16n8k16.row.col.f32.f16.f16.f32 "
        "{%0,%1,%2,%3}, {%4,%5,%6,%7}, {%8,%9}, {%0,%1,%2,%3};"
        : "+f"(c[0]), "+f"(c[1]), "+f"(c[2]), "+f"(c[3])
        : "r"(a[0]), "r"(a[1]), "r"(a[2]), "r"(a[3]), "r"(b[0]), "r"(b[1]));
}
__device__ __forceinline__ void mma_f16(u32* c, const u32* a, const u32* b) {
    asm volatile(
        "mma.sync.aligned.m16n8k16.row.col.f16.f16.f16.f16 "
        "{%0,%1}, {%2,%3,%4,%5}, {%6,%7}, {%0,%1};"
        : "+r"(c[0]), "+r"(c[1])
        : "r"(a[0]), "r"(a[1]), "r"(a[2]), "r"(a[3]), "r"(b[0]), "r"(b[1]));
}

__device__ __forceinline__ float silu(float x) { return x / (1.f + expf(-x)); }

// =====================================================================
// split_all_kernel: grid 8224, coarse (4 float4/thread for conversions).
// [0,1024): X split2 ; [1024,1056): Wr split2 ;
// [1056,2080): Wg ; [2080,3104): Wu ; [3104,4128): Wd (split1) ;
// [4128,8224): zero `out` (rides for free; out untouched until tail).
// Block 0 resets g_done_rt.
// =====================================================================
__global__ void split_all_kernel(const float* __restrict__ X,
                                 const float* __restrict__ Wr,
                                 const float* __restrict__ Wg,
                                 const float* __restrict__ Wu,
                                 const float* __restrict__ Wd,
                                 u16* __restrict__ Xh, u16* __restrict__ Xl,
                                 u16* __restrict__ Wrh, u16* __restrict__ Wrl,
                                 u16* __restrict__ Wgh, u16* __restrict__ Wuh,
                                 u16* __restrict__ Wdh,
                                 float* __restrict__ out)
{
    const int b = blockIdx.x;
    const int tid = threadIdx.x;
    if (b == 0 && tid == 0) g_done_rt = 0u;

    if (b < 1056) {
        const float* src; u16 *hi, *lo; int base;
        if (b < 1024) { src = X;  hi = Xh;  lo = Xl;  base = b * 1024; }
        else          { src = Wr; hi = Wrh; lo = Wrl; base = (b - 1024) * 1024; }
        #pragma unroll
        for (int k = 0; k < 4; k++) {
            const int i = base + k * 256 + tid;
            float4 v = ((const float4*)src)[i];
            __half hx = __float2half_rn(v.x), hy = __float2half_rn(v.y);
            __half hz = __float2half_rn(v.z), hw = __float2half_rn(v.w);
            __half lx = __float2half_rn(v.x - __half2float(hx));
            __half ly = __float2half_rn(v.y - __half2float(hy));
            __half lz = __float2half_rn(v.z - __half2float(hz));
            __half lw = __float2half_rn(v.w - __half2float(hw));
            __half2 h0 = __halves2half2(hx, hy), h1 = __halves2half2(hz, hw);
            __half2 l0 = __halves2half2(lx, ly), l1 = __halves2half2(lz, lw);
            ((uint2*)hi)[i] = make_uint2(*(u32*)&h0, *(u32*)&h1);
            ((uint2*)lo)[i] = make_uint2(*(u32*)&l0, *(u32*)&l1);
        }
    } else if (b < 4128) {
        const float* src; u16* dst; int base;
        if (b < 2080)      { src = Wg; dst = Wgh; base = (b - 1056) * 1024; }
        else if (b < 3104) { src = Wu; dst = Wuh; base = (b - 2080) * 1024; }
        else               { src = Wd; dst = Wdh; base = (b - 3104) * 1024; }
        #pragma unroll
        for (int k = 0; k < 4; k++) {
            const int i = base + k * 256 + tid;
            float4 v = ((const float4*)src)[i];
            __half2 h0 = __halves2half2(__float2half_rn(v.x), __float2half_rn(v.y));
            __half2 h1 = __halves2half2(__float2half_rn(v.z), __float2half_rn(v.w));
            ((uint2*)dst)[i] = make_uint2(*(u32*)&h0, *(u32*)&h1);
        }
    } else {
        ((float4*)out)[(b - 4128) * 256 + tid] = make_float4(0.f, 0.f, 0.f, 0.f);
    }
}

#define PITCH 80
#define PLANE128 10240                // 128 rows * 80
#define PLANE64  5120                 // 64 rows * 80

// =====================================================================
// mlp1_kernel (R8-proven, unchanged): grid (32, 66), 256 thr, occ 2.
//  y < 64 : fused gate/up — Hh = f16(silu(X@Wg^T) * (X@Wu^T))
//  y >= 64: router (fp16x3) — logits columns [(y-64)*64 .. +64)
// =====================================================================
#define STG_GU 20480
#define STG_R  30720
#define SMEM_MLP1 61440

__global__ __launch_bounds__(256, 2)
void mlp1_kernel(const u16* __restrict__ Xh, const u16* __restrict__ Xl,
                 const u16* __restrict__ Wgh, const u16* __restrict__ Wuh,
                 const u16* __restrict__ Wrh, const u16* __restrict__ Wrl,
                 u16* __restrict__ Hh, float* __restrict__ logits)
{
    extern __shared__ char sm[];
    const u32 sb = smem_u32(sm);
    const int tid  = threadIdx.x;
    const int lane = tid & 31;
    const int wid  = tid >> 5;
    const int row0 = blockIdx.x * 128;
    const int warpM = (wid & 3) * 32;
    const int warpN = (wid >> 2) * 32;

    const int lrA = tid >> 1;
    const int cA  = (tid & 1) * 2;
    const int lrB = tid >> 2;
    const int cB  = tid & 3;

    const int l4 = lane & 15;
    const u32 aRowOff = (u32)((lane & 15) * PITCH + ((lane >> 4) << 4));
    const u32 bRowOff = (u32)((l4 & 7) * PITCH + ((l4 >> 3) << 4));

    const int NS = HID >> 5;

    if (blockIdx.y < 64) {
        const int col0 = blockIdx.y * 64;

        auto load_stage = [&](int kt, int buf) {
            const u32 so = sb + buf * STG_GU;
            const size_t goA = (size_t)(row0 + lrA) * HID + kt * 32;
            cp16(so + lrA * PITCH + cA * 16,       Xh + goA + cA * 8);
            cp16(so + lrA * PITCH + (cA + 1) * 16, Xh + goA + (cA + 1) * 8);
            const size_t goB = (size_t)(col0 + lrB) * HID + kt * 32;
            cp16(so + PLANE128 + lrB * PITCH + cB * 16,            Wgh + goB + cB * 8);
            cp16(so + PLANE128 + PLANE64 + lrB * PITCH + cB * 16,  Wuh + goB + cB * 8);
        };

        float accG[2][4][4], accU[2][4][4];
        #pragma unroll
        for (int i = 0; i < 2; i++)
            #pragma unroll
            for (int j = 0; j < 4; j++)
                #pragma unroll
                for (int t = 0; t < 4; t++) { accG[i][j][t] = 0.f; accU[i][j][t] = 0.f; }

        load_stage(0, 0); CP_COMMIT();
        load_stage(1, 1); CP_COMMIT();

        for (int s = 0; s < NS; s++) {
            const int buf = s % 3;
            CP_WAIT(1);
            __syncthreads();
            if (s + 2 < NS) load_stage(s + 2, (s + 2) % 3);
            CP_COMMIT();

            const u32 stg = sb + buf * STG_GU;
            #pragma unroll
            for (int ks = 0; ks < 2; ks++) {
                const u32 kb = ks * 32;
                u32 ah[2][4], bg[4][2], bu[4][2];
                #pragma unroll
                for (int i = 0; i < 2; i++)
                    ldsm_x4(ah[i][0], ah[i][1], ah[i][2], ah[i][3],
                            stg + (warpM + i * 16) * PITCH + kb + aRowOff);
                #pragma unroll
                for (int j = 0; j < 4; j++) {
                    const u32 rb = stg + PLANE128 + (warpN + j * 8) * PITCH + kb + bRowOff;
                    ldsm_x2(bg[j][0], bg[j][1], rb);
                    ldsm_x2(bu[j][0], bu[j][1], rb + PLANE64);
                }
                #pragma unroll
                for (int i = 0; i < 2; i++)
                    #pragma unroll
                    for (int j = 0; j < 4; j++) {
                        mma_f32(accG[i][j], ah[i], bg[j]);
                        mma_f32(accU[i][j], ah[i], bu[j]);
                    }
            }
        }

        #pragma unroll
        for (int i = 0; i < 2; i++) {
            #pragma unroll
            for (int j = 0; j < 4; j++) {
                const int r = row0 + warpM + i * 16 + (lane >> 2);
                const int c = col0 + warpN + j * 8 + (lane & 3) * 2;
                #pragma unroll
                for (int half = 0; half < 2; half++) {
                    const int rr = r + half * 8;
                    const float gg0 = accG[i][j][half * 2 + 0];
                    const float gg1 = accG[i][j][half * 2 + 1];
                    const float uu0 = accU[i][j][half * 2 + 0];
                    const float uu1 = accU[i][j][half * 2 + 1];
                    __half2 hp = __halves2half2(__float2half_rn(silu(gg0) * uu0),
                                                __float2half_rn(silu(gg1) * uu1));
                    ((u32*)Hh)[((size_t)rr * INTER + c) >> 1] = *(u32*)&hp;
                }
            }
        }
    } else {
        const int col0 = (blockIdx.y - 64) * 64;

        auto load_stage = [&](int kt, int buf) {
            const u32 so = sb + buf * STG_R;
            const size_t goA = (size_t)(row0 + lrA) * HID + kt * 32;
            cp16(so + lrA * PITCH + cA * 16,                  Xh + goA + cA * 8);
            cp16(so + lrA * PITCH + (cA + 1) * 16,            Xh + goA + (cA + 1) * 8);
            cp16(so + PLANE128 + lrA * PITCH + cA * 16,       Xl + goA + cA * 8);
            cp16(so + PLANE128 + lrA * PITCH + (cA + 1) * 16, Xl + goA + (cA + 1) * 8);
            const size_t goB = (size_t)(col0 + lrB) * HID + kt * 32;
            cp16(so + 2 * PLANE128 + lrB * PITCH + cB * 16,           Wrh + goB + cB * 8);
            cp16(so + 2 * PLANE128 + PLANE64 + lrB * PITCH + cB * 16, Wrl + goB + cB * 8);
        };

        float acc[2][4][4];
        u32   accX[2][4][2];
        #pragma unroll
        for (int i = 0; i < 2; i++)
            #pragma unroll
            for (int j = 0; j < 4; j++) {
                #pragma unroll
                for (int t = 0; t < 4; t++) acc[i][j][t] = 0.f;
                accX[i][j][0] = 0u; accX[i][j][1] = 0u;
            }

        load_stage(0, 0); CP_COMMIT();

        for (int s = 0; s < NS; s++) {
            const int buf = s & 1;
            if (s + 1 < NS) load_stage(s + 1, (s + 1) & 1);
            CP_COMMIT();
            CP_WAIT(1);
            __syncthreads();

            const u32 stg = sb + buf * STG_R;
            #pragma unroll
            for (int ks = 0; ks < 2; ks++) {
                const u32 kb = ks * 32;
                u32 ah[2][4], al[2][4], bh[4][2], bl[4][2];
                #pragma unroll
                for (int i = 0; i < 2; i++) {
                    const u32 ra = stg + (warpM + i * 16) * PITCH + kb + aRowOff;
                    ldsm_x4(ah[i][0], ah[i][1], ah[i][2], ah[i][3], ra);
                    ldsm_x4(al[i][0], al[i][1], al[i][2], al[i][3], ra + PLANE128);
                }
                #pragma unroll
                for (int j = 0; j < 4; j++) {
                    const u32 rb = stg + 2 * PLANE128 + (warpN + j * 8) * PITCH + kb + bRowOff;
                    ldsm_x2(bh[j][0], bh[j][1], rb);
                    ldsm_x2(bl[j][0], bl[j][1], rb + PLANE64);
                }
                #pragma unroll
                for (int i = 0; i < 2; i++)
                    #pragma unroll
                    for (int j = 0; j < 4; j++) {
                        mma_f32(acc[i][j], ah[i], bh[j]);
                        mma_f16(accX[i][j], ah[i], bl[j]);
                        mma_f16(accX[i][j], al[i], bh[j]);
                    }
            }
            __syncthreads();
        }

        #pragma unroll
        for (int i = 0; i < 2; i++) {
            #pragma unroll
            for (int j = 0; j < 4; j++) {
                float2 x0 = __half22float2(*(__half2*)&accX[i][j][0]);
                float2 x1 = __half22float2(*(__half2*)&accX[i][j][1]);
                const float vv[4] = { acc[i][j][0] + x0.x, acc[i][j][1] + x0.y,
                                      acc[i][j][2] + x1.x, acc[i][j][3] + x1.y };
                const int r = row0 + warpM + i * 16 + (lane >> 2);
                const int c = col0 + warpN + j * 8 + (lane & 3) * 2;
                #pragma unroll
                for (int half = 0; half < 2; half++) {
                    const int rr = r + half * 8;
                    *(float2*)(logits + (size_t)rr * 128 + c) =
                        make_float2(vv[half * 2 + 0], vv[half * 2 + 1]);
                }
            }
        }
    }
}

// =====================================================================
// routing helper
// =====================================================================
__device__ __forceinline__ void top8_insert(float v, int idx, float* hv, int* hi) {
    if (v <= hv[7]) return;
    int p = 7;
    #pragma unroll
    for (int q = 7; q > 0; q--) {
        if (v > hv[q-1]) { hv[q] = hv[q-1]; hi[q] = hi[q-1]; p = q - 1; }
    }
    hv[p] = v; hi[p] = idx;
}

// =====================================================================
// tail_kernel: grid 16 + 256 + 4096, occ 2.
//  bid < 16   : routing for tokens [bid*256, +256) ; release g_done_rt
//  bid < 272  : down GEMM tile (128x128, 4-stage, atomicAdd epilogue)
//  bid >= 272 : experts token; read-only poll on g_done_rt==16 (only
//               ~24 wave-1 CTAs ever loop, ~4us, plain loads — benign),
//               then gather + atomicAdd epilogue.
// out pre-zeroed in split launch; each element gets EXACTLY two atomic
// adds (one down, one experts) -> bitwise deterministic.
// =====================================================================
#define STG1 20480                    // 2 x PLANE128
#define SMEM_TAIL (4 * STG1)          // 81920

__global__ __launch_bounds__(256, 2)
void tail_kernel(const u16* __restrict__ A_h, const u16* __restrict__ B_h,
                 float* __restrict__ out,
                 const float* __restrict__ X,
                 const float* __restrict__ down_e,
                 const float* __restrict__ up_e,
                 const float* __restrict__ logits)
{
    extern __shared__ char sm[];
    const int tid  = threadIdx.x;

    if (blockIdx.x < 16) {
        // ---------------- routing ----------------
        const int m = blockIdx.x * 256 + tid;
        const float* px = logits + (size_t)(m >> 1) * 128 + (m & 1) * 64;
        const float* py = logits + (size_t)(2048 + (m >> 1)) * 128 + (m & 1) * 64;

        float vx[8], vy[8];
        int   ix[8], iy[8];
        #pragma unroll
        for (int t = 0; t < 8; t++) { vx[t] = -3.4e38f; vy[t] = -3.4e38f; ix[t] = 0; iy[t] = 0; }
        for (int k = 0; k < NKEYS; k++) top8_insert(px[k], k, vx, ix);
        for (int k = 0; k < NKEYS; k++) top8_insert(py[k], k, vy, iy);

        float sv[8]; int sa[8];
        #pragma unroll
        for (int t = 0; t < 8; t++) { sv[t] = -3.4e38f; sa[t] = 0; }
        for (int a = 0; a < 8; a++)
            for (int bq = 0; bq < 8; bq++)
                top8_insert(vx[a] + vy[bq], a * 8 + bq, sv, sa);

        float mx = sv[0];
        float e[8], s = 0.f;
        #pragma unroll
        for (int t = 0; t < 8; t++) { e[t] = expf(sv[t] - mx); s += e[t]; }
        float w[8], s2 = 0.f;
        #pragma unroll
        for (int t = 0; t < 8; t++) { w[t] = e[t] / s; s2 += w[t]; }
        #pragma unroll
        for (int t = 0; t < 8; t++) {
            int a = sa[t] >> 3, bq = sa[t] & 7;
            g_tidx[m * TOPK + t] = ix[a] * NKEYS + iy[bq];
            g_tw[m * TOPK + t]   = w[t] / s2;
        }
        __threadfence();
        __syncthreads();
        if (tid == 0) atomicAdd(&g_done_rt, 1u);

    } else if (blockIdx.x < 272) {
        // ---------------- down GEMM tile ----------------
        const u32 sb = smem_u32(sm);
        const int lane = tid & 31;
        const int wid  = tid >> 5;
        const int d = blockIdx.x - 16;
        const int row0 = (d & 31) * 128;
        const int col0 = (d >> 5) * 128;
        const int warpM = (wid >> 2) * 64;
        const int warpN = (wid & 3) * 32;
        const int K = INTER, ldC = HID;

        const int f  = tid * 2;
        const int lr = f >> 2;
        const int c0 = f & 3;

        const int NS = K >> 5;

        auto load_stage = [&](int kt, int buf) {
            const size_t goA = (size_t)(row0 + lr) * K + kt * 32;
            const size_t goB = (size_t)(col0 + lr) * K + kt * 32;
            const u32 so = sb + buf * STG1 + lr * PITCH;
            cp16(so + c0 * 16,                  A_h + goA + c0 * 8);
            cp16(so + (c0 + 1) * 16,            A_h + goA + (c0 + 1) * 8);
            cp16(so + PLANE128 + c0 * 16,       B_h + goB + c0 * 8);
            cp16(so + PLANE128 + (c0 + 1) * 16, B_h + goB + (c0 + 1) * 8);
        };

        float acc[4][4][4];
        #pragma unroll
        for (int i = 0; i < 4; i++)
            #pragma unroll
            for (int j = 0; j < 4; j++)
                #pragma unroll
                for (int t = 0; t < 4; t++) acc[i][j][t] = 0.f;

        const int l4 = lane & 15;
        const u32 aRowOff = (u32)((lane & 15) * PITCH + ((lane >> 4) << 4));
        const u32 bRowOff = (u32)((l4 & 7) * PITCH + ((l4 >> 3) << 4));

        load_stage(0, 0); CP_COMMIT();
        load_stage(1, 1); CP_COMMIT();
        load_stage(2, 2); CP_COMMIT();

        for (int s = 0; s < NS; s++) {
            const int buf = s & 3;
            CP_WAIT(2);
            __syncthreads();
            if (s + 3 < NS) load_stage(s + 3, (s + 3) & 3);
            CP_COMMIT();

            const u32 stg = sb + buf * STG1;
            #pragma unroll
            for (int ks = 0; ks < 2; ks++) {
                const u32 kb = ks * 32;
                u32 ah[4][4], bh[4][2];
                #pragma unroll
                for (int i = 0; i < 4; i++)
                    ldsm_x4(ah[i][0], ah[i][1], ah[i][2], ah[i][3],
                            stg + (warpM + i * 16) * PITCH + kb + aRowOff);
                #pragma unroll
                for (int j = 0; j < 4; j++)
                    ldsm_x2(bh[j][0], bh[j][1],
                            stg + PLANE128 + (warpN + j * 8) * PITCH + kb + bRowOff);
                #pragma unroll
                for (int i = 0; i < 4; i++)
                    #pragma unroll
                    for (int j = 0; j < 4; j++) mma_f32(acc[i][j], ah[i], bh[j]);
            }
        }

        #pragma unroll
        for (int i = 0; i < 4; i++) {
            #pragma unroll
            for (int j = 0; j < 4; j++) {
                const int r = row0 + warpM + i * 16 + (lane >> 2);
                const int c = col0 + warpN + j * 8 + (lane & 3) * 2;
                #pragma unroll
                for (int half = 0; half < 2; half++) {
                    const int rr = r + half * 8;
                    atomicAdd(out + (size_t)rr * ldC + c,     acc[i][j][half * 2 + 0]);
                    atomicAdd(out + (size_t)rr * ldC + c + 1, acc[i][j][half * 2 + 1]);
                }
            }
        }
    } else {
        // ---------------- experts token ----------------
        const int m = blockIdx.x - 272;
        float4* xs4 = (float4*)sm;
        float*  ews = (float*)(sm + 4096);

        // acquire: routing blocks (ids 0-15, wave 1) must be done.
        if (tid == 0) {
            while (*(volatile u32*)&g_done_rt < 16u) { __nanosleep(64); }
        }
        __syncthreads();
        __threadfence();

        xs4[tid] = ((const float4*)(X + (size_t)m * HID))[tid];
        __syncthreads();

        const float* xs = (const float*)xs4;
        const int wid  = tid >> 5;
        const int lane = tid & 31;

        {
            int e = g_tidx[m * TOPK + wid];
            const float* d = down_e + (size_t)e * HID;
            float s = 0.f;
            for (int k = lane; k < HID; k += 32) s = fmaf(d[k], xs[k], s);
            #pragma unroll
            for (int o = 16; o; o >>= 1) s += __shfl_xor_sync(0xffffffffu, s, o);
            if (lane == 0) {
                float sig = s / (1.f + expf(-s));
                ews[wid] = sig * g_tw[m * TOPK + wid];
            }
        }
        __syncthreads();

        float4 acc = make_float4(0.f, 0.f, 0.f, 0.f);
        #pragma unroll
        for (int k = 0; k < TOPK; k++) {
            int e = g_tidx[m * TOPK + k];
            float w = ews[k];
            float4 u = ((const float4*)(up_e + (size_t)e * HID))[tid];
            acc.x = fmaf(w, u.x, acc.x);
            acc.y = fmaf(w, u.y, acc.y);
            acc.z = fmaf(w, u.z, acc.z);
            acc.w = fmaf(w, u.w, acc.w);
        }
        float* dst = out + (size_t)m * HID + tid * 4;
        atomicAdd(dst + 0, acc.x);
        atomicAdd(dst + 1, acc.y);
        atomicAdd(dst + 2, acc.z);
        atomicAdd(dst + 3, acc.w);
    }
}

// ---------------- launch ----------------
static void* sym(const void* s) { void* p = nullptr; cudaGetSymbolAddress(&p, s); return p; }

extern "C" void kernel_launch(void* const* d_in, const int* in_sizes, int n_in,
                              void* d_out, int out_size)
{
    const float* X        = (const float*)d_in[0];
    const float* w_gate   = (const float*)d_in[1];
    const float* w_up     = (const float*)d_in[2];
    const float* w_down   = (const float*)d_in[3];
    const float* w_router = (const float*)d_in[4];
    const float* down_e   = (const float*)d_in[5];
    const float* up_e     = (const float*)d_in[6];

    float* out    = (float*)d_out;
    float* logits = (float*)d_out + (size_t)NTOK * HID;

    u16 *Xh = (u16*)sym(g_Xh),  *Xl = (u16*)sym(g_Xl);
    u16 *Wgh = (u16*)sym(g_Wgh);
    u16 *Wuh = (u16*)sym(g_Wuh);
    u16 *Wdh = (u16*)sym(g_Wdh);
    u16 *Wrh = (u16*)sym(g_Wrh), *Wrl = (u16*)sym(g_Wrl);
    u16 *Hh = (u16*)sym(g_Hh);

    cudaFuncSetAttribute(mlp1_kernel, cudaFuncAttributeMaxDynamicSharedMemorySize, SMEM_MLP1);
    cudaFuncSetAttribute(tail_kernel, cudaFuncAttributeMaxDynamicSharedMemorySize, SMEM_TAIL);

    // 0) splits + zero-out ride + counter reset
    split_all_kernel<<<8224, 256>>>(X, w_router, w_gate, w_up, w_down,
                                    Xh, Xl, Wrh, Wrl, Wgh, Wuh, Wdh, out);
    // 1) fused gate/up + router
    mlp1_kernel<<<dim3(NTOK / 128, 66), 256, SMEM_MLP1>>>(
        Xh, Xl, Wgh, Wuh, Wrh, Wrl, Hh, logits);
    // 2) routing + down GEMM + experts, one launch
    tail_kernel<<<16 + 256 + NTOK, 256, SMEM_TAIL>>>(Hh, Wdh, out, X,
                                                     down_e, up_e, logits);
    (void)in_sizes; (void)n_in; (void)out_size;
}

// round 17
// speedup vs baseline: 1.6055x; 1.0699x over previous
#include <cuda_runtime.h>
#include <cuda_fp16.h>
#include <cstdint>
#include <math.h>

#define HID    1024
#define INTER  4096
#define NTOK   4096
#define NKEYS  64
#define TOPK   8

typedef unsigned short u16;
typedef unsigned int   u32;

// ---------------- scratch (no allocations allowed) ----------------
__device__ __align__(16) static u16   g_Xh[(size_t)NTOK * HID];
__device__ __align__(16) static u16   g_Xl[(size_t)NTOK * HID];
__device__ __align__(16) static u16   g_Wgh[(size_t)INTER * HID];
__device__ __align__(16) static u16   g_Wuh[(size_t)INTER * HID];
__device__ __align__(16) static u16   g_Wdh[(size_t)HID * INTER];
__device__ __align__(16) static u16   g_Wrh[(size_t)128 * HID];
__device__ __align__(16) static u16   g_Wrl[(size_t)128 * HID];
__device__ __align__(16) static u16   g_Hh[(size_t)NTOK * INTER];
__device__ static int   g_tidx[NTOK * TOPK];
__device__ static float g_tw[NTOK * TOPK];
__device__ static u32   g_done_r;         // router blocks done (64)
__device__ static u32   g_done_rt;        // routing blocks done (16)
__device__ static u32   g_done_row[32];   // GU col-tiles done per row-block (64 each)

// ---------------- helpers ----------------
__device__ __forceinline__ u32 smem_u32(const void* p) {
    u32 a;
    asm("{ .reg .u64 t; cvta.to.shared.u64 t, %1; cvt.u32.u64 %0, t; }" : "=r"(a) : "l"(p));
    return a;
}

__device__ __forceinline__ void cp16(u32 dst, const void* src) {
    asm volatile("cp.async.cg.shared.global [%0], [%1], 16;" :: "r"(dst), "l"(src));
}
#define CP_COMMIT() asm volatile("cp.async.commit_group;" ::: "memory")
#define CP_WAIT(n)  asm volatile("cp.async.wait_group %0;" :: "n"(n) : "memory")

__device__ __forceinline__ void ldsm_x4(u32& r0, u32& r1, u32& r2, u32& r3, u32 addr) {
    asm volatile("ldmatrix.sync.aligned.m8n8.x4.shared.b16 {%0,%1,%2,%3}, [%4];"
                 : "=r"(r0), "=r"(r1), "=r"(r2), "=r"(r3) : "r"(addr));
}
__device__ __forceinline__ void ldsm_x2(u32& r0, u32& r1, u32 addr) {
    asm volatile("ldmatrix.sync.aligned.m8n8.x2.shared.b16 {%0,%1}, [%2];"
                 : "=r"(r0), "=r"(r1) : "r"(addr));
}

__device__ __forceinline__ void mma_f32(float* c, const u32* a, const u32* b) {
    asm volatile(
        "mma.sync.aligned.m16n8k16.row.col.f32.f16.f16.f32 "
        "{%0,%1,%2,%3}, {%4,%5,%6,%7}, {%8,%9}, {%0,%1,%2,%3};"
        : "+f"(c[0]), "+f"(c[1]), "+f"(c[2]), "+f"(c[3])
        : "r"(a[0]), "r"(a[1]), "r"(a[2]), "r"(a[3]), "r"(b[0]), "r"(b[1]));
}
__device__ __forceinline__ void mma_f16(u32* c, const u32* a, const u32* b) {
    asm volatile(
        "mma.sync.aligned.m16n8k16.row.col.f16.f16.f16.f16 "
        "{%0,%1}, {%2,%3,%4,%5}, {%6,%7}, {%0,%1};"
        : "+r"(c[0]), "+r"(c[1])
        : "r"(a[0]), "r"(a[1]), "r"(a[2]), "r"(a[3]), "r"(b[0]), "r"(b[1]));
}

__device__ __forceinline__ float silu(float x) { return x / (1.f + expf(-x)); }

// =====================================================================
// split_all_kernel: grid 8224 (unchanged from R16) + counter resets.
// [0,1024): X split2 ; [1024,1056): Wr split2 ;
// [1056,2080): Wg ; [2080,3104): Wu ; [3104,4128): Wd (split1) ;
// [4128,8224): zero `out`.
// =====================================================================
__global__ void split_all_kernel(const float* __restrict__ X,
                                 const float* __restrict__ Wr,
                                 const float* __restrict__ Wg,
                                 const float* __restrict__ Wu,
                                 const float* __restrict__ Wd,
                                 u16* __restrict__ Xh, u16* __restrict__ Xl,
                                 u16* __restrict__ Wrh, u16* __restrict__ Wrl,
                                 u16* __restrict__ Wgh, u16* __restrict__ Wuh,
                                 u16* __restrict__ Wdh,
                                 float* __restrict__ out)
{
    const int b = blockIdx.x;
    const int tid = threadIdx.x;
    if (b == 0) {
        if (tid == 0) { g_done_r = 0u; g_done_rt = 0u; }
        if (tid < 32) g_done_row[tid] = 0u;
    }

    if (b < 1056) {
        const float* src; u16 *hi, *lo; int base;
        if (b < 1024) { src = X;  hi = Xh;  lo = Xl;  base = b * 1024; }
        else          { src = Wr; hi = Wrh; lo = Wrl; base = (b - 1024) * 1024; }
        #pragma unroll
        for (int k = 0; k < 4; k++) {
            const int i = base + k * 256 + tid;
            float4 v = ((const float4*)src)[i];
            __half hx = __float2half_rn(v.x), hy = __float2half_rn(v.y);
            __half hz = __float2half_rn(v.z), hw = __float2half_rn(v.w);
            __half lx = __float2half_rn(v.x - __half2float(hx));
            __half ly = __float2half_rn(v.y - __half2float(hy));
            __half lz = __float2half_rn(v.z - __half2float(hz));
            __half lw = __float2half_rn(v.w - __half2float(hw));
            __half2 h0 = __halves2half2(hx, hy), h1 = __halves2half2(hz, hw);
            __half2 l0 = __halves2half2(lx, ly), l1 = __halves2half2(lz, lw);
            ((uint2*)hi)[i] = make_uint2(*(u32*)&h0, *(u32*)&h1);
            ((uint2*)lo)[i] = make_uint2(*(u32*)&l0, *(u32*)&l1);
        }
    } else if (b < 4128) {
        const float* src; u16* dst; int base;
        if (b < 2080)      { src = Wg; dst = Wgh; base = (b - 1056) * 1024; }
        else if (b < 3104) { src = Wu; dst = Wuh; base = (b - 2080) * 1024; }
        else               { src = Wd; dst = Wdh; base = (b - 3104) * 1024; }
        #pragma unroll
        for (int k = 0; k < 4; k++) {
            const int i = base + k * 256 + tid;
            float4 v = ((const float4*)src)[i];
            __half2 h0 = __halves2half2(__float2half_rn(v.x), __float2half_rn(v.y));
            __half2 h1 = __halves2half2(__float2half_rn(v.z), __float2half_rn(v.w));
            ((uint2*)dst)[i] = make_uint2(*(u32*)&h0, *(u32*)&h1);
        }
    } else {
        ((float4*)out)[(b - 4128) * 256 + tid] = make_float4(0.f, 0.f, 0.f, 0.f);
    }
}

#define PITCH 80
#define PLANE128 10240
#define PLANE64  5120
#define STG_GU 20480                  // GU stage (3 stages = 61440)
#define STG_R  30720                  // router stage (2 stages = 61440)
#define STG_D  20480                  // down stage (4 stages = 81920)
#define SMEM_MEGA 81920

__device__ __forceinline__ void top8_insert(float v, int idx, float* hv, int* hi) {
    if (v <= hv[7]) return;
    int p = 7;
    #pragma unroll
    for (int q = 7; q > 0; q--) {
        if (v > hv[q-1]) { hv[q] = hv[q-1]; hi[q] = hi[q-1]; p = q - 1; }
    }
    hv[p] = v; hi[p] = idx;
}

// =====================================================================
// mega_kernel: grid 6480, 256 thr, occ 2, smem 81920.
// IDs strictly ordered so every poller waits only on lower-ID blocks:
//  [0,64)      router (fp16x3) -> logits ; release g_done_r
//  [64,2112)   GU ROW-MAJOR (q=bid-64: row=q>>6, col=q&63) -> Hh ;
//              release g_done_row[row]
//  [2112,2128) routing ; poll g_done_r==64 (satisfied long before) ;
//              release g_done_rt
//  [2128,2384) down (d=bid-2128: row=d>>3, col=d&7) ; volatile-poll
//              g_done_row[row]==64 ; atomicAdd epilogue
//  [2384,6480) experts ; volatile-poll g_done_rt==16 ; atomicAdd epilogue
// out pre-zeroed; exactly two atomic adds per element -> deterministic.
// =====================================================================
__global__ __launch_bounds__(256, 2)
void mega_kernel(const u16* __restrict__ Xh, const u16* __restrict__ Xl,
                 const u16* __restrict__ Wgh, const u16* __restrict__ Wuh,
                 const u16* __restrict__ Wrh, const u16* __restrict__ Wrl,
                 u16* __restrict__ Hh, float* __restrict__ logits,
                 float* __restrict__ out,
                 const float* __restrict__ X,
                 const float* __restrict__ down_e,
                 const float* __restrict__ up_e)
{
    extern __shared__ char sm[];
    const int bidx = blockIdx.x;
    const int tid  = threadIdx.x;
    const u32 sb   = smem_u32(sm);
    const int lane = tid & 31;
    const int wid  = tid >> 5;
    const int l4   = lane & 15;
    const u32 aRowOff = (u32)((lane & 15) * PITCH + ((lane >> 4) << 4));
    const u32 bRowOff = (u32)((l4 & 7) * PITCH + ((l4 >> 3) << 4));

    if (bidx < 64) {
        // ================= router (fp16x3) =================
        const int row0 = (bidx & 31) * 128;
        const int col0 = (bidx >> 5) * 64;
        const int warpM = (wid & 3) * 32;
        const int warpN = (wid >> 2) * 32;
        const int lrA = tid >> 1;
        const int cA  = (tid & 1) * 2;
        const int lrB = tid >> 2;
        const int cB  = tid & 3;
        const int NS = HID >> 5;

        auto load_stage = [&](int kt, int buf) {
            const u32 so = sb + buf * STG_R;
            const size_t goA = (size_t)(row0 + lrA) * HID + kt * 32;
            cp16(so + lrA * PITCH + cA * 16,                  Xh + goA + cA * 8);
            cp16(so + lrA * PITCH + (cA + 1) * 16,            Xh + goA + (cA + 1) * 8);
            cp16(so + PLANE128 + lrA * PITCH + cA * 16,       Xl + goA + cA * 8);
            cp16(so + PLANE128 + lrA * PITCH + (cA + 1) * 16, Xl + goA + (cA + 1) * 8);
            const size_t goB = (size_t)(col0 + lrB) * HID + kt * 32;
            cp16(so + 2 * PLANE128 + lrB * PITCH + cB * 16,           Wrh + goB + cB * 8);
            cp16(so + 2 * PLANE128 + PLANE64 + lrB * PITCH + cB * 16, Wrl + goB + cB * 8);
        };

        float acc[2][4][4];
        u32   accX[2][4][2];
        #pragma unroll
        for (int i = 0; i < 2; i++)
            #pragma unroll
            for (int j = 0; j < 4; j++) {
                #pragma unroll
                for (int t = 0; t < 4; t++) acc[i][j][t] = 0.f;
                accX[i][j][0] = 0u; accX[i][j][1] = 0u;
            }

        load_stage(0, 0); CP_COMMIT();

        for (int s = 0; s < NS; s++) {
            const int buf = s & 1;
            if (s + 1 < NS) load_stage(s + 1, (s + 1) & 1);
            CP_COMMIT();
            CP_WAIT(1);
            __syncthreads();

            const u32 stg = sb + buf * STG_R;
            #pragma unroll
            for (int ks = 0; ks < 2; ks++) {
                const u32 kb = ks * 32;
                u32 ah[2][4], al[2][4], bh[4][2], bl[4][2];
                #pragma unroll
                for (int i = 0; i < 2; i++) {
                    const u32 ra = stg + (warpM + i * 16) * PITCH + kb + aRowOff;
                    ldsm_x4(ah[i][0], ah[i][1], ah[i][2], ah[i][3], ra);
                    ldsm_x4(al[i][0], al[i][1], al[i][2], al[i][3], ra + PLANE128);
                }
                #pragma unroll
                for (int j = 0; j < 4; j++) {
                    const u32 rbq = stg + 2 * PLANE128 + (warpN + j * 8) * PITCH + kb + bRowOff;
                    ldsm_x2(bh[j][0], bh[j][1], rbq);
                    ldsm_x2(bl[j][0], bl[j][1], rbq + PLANE64);
                }
                #pragma unroll
                for (int i = 0; i < 2; i++)
                    #pragma unroll
                    for (int j = 0; j < 4; j++) {
                        mma_f32(acc[i][j], ah[i], bh[j]);
                        mma_f16(accX[i][j], ah[i], bl[j]);
                        mma_f16(accX[i][j], al[i], bh[j]);
                    }
            }
            __syncthreads();
        }

        #pragma unroll
        for (int i = 0; i < 2; i++) {
            #pragma unroll
            for (int j = 0; j < 4; j++) {
                float2 x0 = __half22float2(*(__half2*)&accX[i][j][0]);
                float2 x1 = __half22float2(*(__half2*)&accX[i][j][1]);
                const float vv[4] = { acc[i][j][0] + x0.x, acc[i][j][1] + x0.y,
                                      acc[i][j][2] + x1.x, acc[i][j][3] + x1.y };
                const int r = row0 + (wid & 3) * 32 + i * 16 + (lane >> 2);
                const int c = col0 + (wid >> 2) * 32 + j * 8 + (lane & 3) * 2;
                #pragma unroll
                for (int half = 0; half < 2; half++) {
                    const int rr = r + half * 8;
                    *(float2*)(logits + (size_t)rr * 128 + c) =
                        make_float2(vv[half * 2 + 0], vv[half * 2 + 1]);
                }
            }
        }
        __threadfence();
        __syncthreads();
        if (tid == 0) atomicAdd(&g_done_r, 1u);

    } else if (bidx < 2112) {
        // ================= gate/up (row-major) =================
        const int q = bidx - 64;
        const int rowT = q >> 6;              // 0..31
        const int row0 = rowT * 128;
        const int col0 = (q & 63) * 64;
        const int warpM = (wid & 3) * 32;
        const int warpN = (wid >> 2) * 32;
        const int lrA = tid >> 1;
        const int cA  = (tid & 1) * 2;
        const int lrB = tid >> 2;
        const int cB  = tid & 3;
        const int NS = HID >> 5;

        auto load_stage = [&](int kt, int buf) {
            const u32 so = sb + buf * STG_GU;
            const size_t goA = (size_t)(row0 + lrA) * HID + kt * 32;
            cp16(so + lrA * PITCH + cA * 16,       Xh + goA + cA * 8);
            cp16(so + lrA * PITCH + (cA + 1) * 16, Xh + goA + (cA + 1) * 8);
            const size_t goB = (size_t)(col0 + lrB) * HID + kt * 32;
            cp16(so + PLANE128 + lrB * PITCH + cB * 16,           Wgh + goB + cB * 8);
            cp16(so + PLANE128 + PLANE64 + lrB * PITCH + cB * 16, Wuh + goB + cB * 8);
        };

        float accG[2][4][4], accU[2][4][4];
        #pragma unroll
        for (int i = 0; i < 2; i++)
            #pragma unroll
            for (int j = 0; j < 4; j++)
                #pragma unroll
                for (int t = 0; t < 4; t++) { accG[i][j][t] = 0.f; accU[i][j][t] = 0.f; }

        load_stage(0, 0); CP_COMMIT();
        load_stage(1, 1); CP_COMMIT();

        for (int s = 0; s < NS; s++) {
            const int buf = s % 3;
            CP_WAIT(1);
            __syncthreads();
            if (s + 2 < NS) load_stage(s + 2, (s + 2) % 3);
            CP_COMMIT();

            const u32 stg = sb + buf * STG_GU;
            #pragma unroll
            for (int ks = 0; ks < 2; ks++) {
                const u32 kb = ks * 32;
                u32 ah[2][4], bg[4][2], bu[4][2];
                #pragma unroll
                for (int i = 0; i < 2; i++)
                    ldsm_x4(ah[i][0], ah[i][1], ah[i][2], ah[i][3],
                            stg + (warpM + i * 16) * PITCH + kb + aRowOff);
                #pragma unroll
                for (int j = 0; j < 4; j++) {
                    const u32 rb = stg + PLANE128 + (warpN + j * 8) * PITCH + kb + bRowOff;
                    ldsm_x2(bg[j][0], bg[j][1], rb);
                    ldsm_x2(bu[j][0], bu[j][1], rb + PLANE64);
                }
                #pragma unroll
                for (int i = 0; i < 2; i++)
                    #pragma unroll
                    for (int j = 0; j < 4; j++) {
                        mma_f32(accG[i][j], ah[i], bg[j]);
                        mma_f32(accU[i][j], ah[i], bu[j]);
                    }
            }
        }

        #pragma unroll
        for (int i = 0; i < 2; i++) {
            #pragma unroll
            for (int j = 0; j < 4; j++) {
                const int r = row0 + warpM + i * 16 + (lane >> 2);
                const int c = col0 + warpN + j * 8 + (lane & 3) * 2;
                #pragma unroll
                for (int half = 0; half < 2; half++) {
                    const int rr = r + half * 8;
                    const float gg0 = accG[i][j][half * 2 + 0];
                    const float gg1 = accG[i][j][half * 2 + 1];
                    const float uu0 = accU[i][j][half * 2 + 0];
                    const float uu1 = accU[i][j][half * 2 + 1];
                    __half2 hp = __halves2half2(__float2half_rn(silu(gg0) * uu0),
                                                __float2half_rn(silu(gg1) * uu1));
                    ((u32*)Hh)[((size_t)rr * INTER + c) >> 1] = *(u32*)&hp;
                }
            }
        }
        __threadfence();
        __syncthreads();
        if (tid == 0) atomicAdd(&g_done_row[rowT], 1u);

    } else if (bidx < 2128) {
        // ================= routing =================
        if (tid == 0) {
            while (*(volatile u32*)&g_done_r < 64u) { __nanosleep(64); }
        }
        __syncthreads();
        __threadfence();

        const int m = (bidx - 2112) * 256 + tid;
        const float* px = logits + (size_t)(m >> 1) * 128 + (m & 1) * 64;
        const float* py = logits + (size_t)(2048 + (m >> 1)) * 128 + (m & 1) * 64;

        float vx[8], vy[8];
        int   ix[8], iy[8];
        #pragma unroll
        for (int t = 0; t < 8; t++) { vx[t] = -3.4e38f; vy[t] = -3.4e38f; ix[t] = 0; iy[t] = 0; }
        for (int k = 0; k < NKEYS; k++) top8_insert(px[k], k, vx, ix);
        for (int k = 0; k < NKEYS; k++) top8_insert(py[k], k, vy, iy);

        float sv[8]; int sa[8];
        #pragma unroll
        for (int t = 0; t < 8; t++) { sv[t] = -3.4e38f; sa[t] = 0; }
        for (int a = 0; a < 8; a++)
            for (int bq = 0; bq < 8; bq++)
                top8_insert(vx[a] + vy[bq], a * 8 + bq, sv, sa);

        float mx = sv[0];
        float e[8], s = 0.f;
        #pragma unroll
        for (int t = 0; t < 8; t++) { e[t] = expf(sv[t] - mx); s += e[t]; }
        float w[8], s2 = 0.f;
        #pragma unroll
        for (int t = 0; t < 8; t++) { w[t] = e[t] / s; s2 += w[t]; }
        #pragma unroll
        for (int t = 0; t < 8; t++) {
            int a = sa[t] >> 3, bq = sa[t] & 7;
            g_tidx[m * TOPK + t] = ix[a] * NKEYS + iy[bq];
            g_tw[m * TOPK + t]   = w[t] / s2;
        }
        __threadfence();
        __syncthreads();
        if (tid == 0) atomicAdd(&g_done_rt, 1u);

    } else if (bidx < 2384) {
        // ================= down GEMM =================
        const int d = bidx - 2128;
        const int rowT = d >> 3;              // 0..31 (matches GU row order)
        const int row0 = rowT * 128;
        const int col0 = (d & 7) * 128;

        if (tid == 0) {
            while (*(volatile u32*)&g_done_row[rowT] < 64u) { __nanosleep(128); }
        }
        __syncthreads();
        __threadfence();

        const int warpM = (wid >> 2) * 64;
        const int warpN = (wid & 3) * 32;
        const int f  = tid * 2;
        const int lr = f >> 2;
        const int c0 = f & 3;
        const int NS = INTER >> 5;

        auto load_stage = [&](int kt, int buf) {
            const size_t goA = (size_t)(row0 + lr) * INTER + kt * 32;
            const size_t goB = (size_t)(col0 + lr) * INTER + kt * 32;
            const u32 so = sb + buf * STG_D + lr * PITCH;
            cp16(so + c0 * 16,                  Hh + goA + c0 * 8);
            cp16(so + (c0 + 1) * 16,            Hh + goA + (c0 + 1) * 8);
            cp16(so + PLANE128 + c0 * 16,       g_Wdh + goB + c0 * 8);
            cp16(so + PLANE128 + (c0 + 1) * 16, g_Wdh + goB + (c0 + 1) * 8);
        };

        float acc[4][4][4];
        #pragma unroll
        for (int i = 0; i < 4; i++)
            #pragma unroll
            for (int j = 0; j < 4; j++)
                #pragma unroll
                for (int t = 0; t < 4; t++) acc[i][j][t] = 0.f;

        load_stage(0, 0); CP_COMMIT();
        load_stage(1, 1); CP_COMMIT();
        load_stage(2, 2); CP_COMMIT();

        for (int s = 0; s < NS; s++) {
            const int buf = s & 3;
            CP_WAIT(2);
            __syncthreads();
            if (s + 3 < NS) load_stage(s + 3, (s + 3) & 3);
            CP_COMMIT();

            const u32 stg = sb + buf * STG_D;
            #pragma unroll
            for (int ks = 0; ks < 2; ks++) {
                const u32 kb = ks * 32;
                u32 ah[4][4], bh[4][2];
                #pragma unroll
                for (int i = 0; i < 4; i++)
                    ldsm_x4(ah[i][0], ah[i][1], ah[i][2], ah[i][3],
                            stg + (warpM + i * 16) * PITCH + kb + aRowOff);
                #pragma unroll
                for (int j = 0; j < 4; j++)
                    ldsm_x2(bh[j][0], bh[j][1],
                            stg + PLANE128 + (warpN + j * 8) * PITCH + kb + bRowOff);
                #pragma unroll
                for (int i = 0; i < 4; i++)
                    #pragma unroll
                    for (int j = 0; j < 4; j++) mma_f32(acc[i][j], ah[i], bh[j]);
            }
        }

        #pragma unroll
        for (int i = 0; i < 4; i++) {
            #pragma unroll
            for (int j = 0; j < 4; j++) {
                const int r = row0 + warpM + i * 16 + (lane >> 2);
                const int c = col0 + warpN + j * 8 + (lane & 3) * 2;
                #pragma unroll
                for (int half = 0; half < 2; half++) {
                    const int rr = r + half * 8;
                    atomicAdd(out + (size_t)rr * HID + c,     acc[i][j][half * 2 + 0]);
                    atomicAdd(out + (size_t)rr * HID + c + 1, acc[i][j][half * 2 + 1]);
                }
            }
        }
    } else {
        // ================= experts =================
        const int m = bidx - 2384;
        float4* xs4 = (float4*)sm;
        float*  ews = (float*)(sm + 4096);

        if (tid == 0) {
            while (*(volatile u32*)&g_done_rt < 16u) { __nanosleep(64); }
        }
        __syncthreads();
        __threadfence();

        xs4[tid] = ((const float4*)(X + (size_t)m * HID))[tid];
        __syncthreads();

        const float* xs = (const float*)xs4;

        {
            int e = g_tidx[m * TOPK + wid];
            const float* dd = down_e + (size_t)e * HID;
            float s = 0.f;
            for (int k = lane; k < HID; k += 32) s = fmaf(dd[k], xs[k], s);
            #pragma unroll
            for (int o = 16; o; o >>= 1) s += __shfl_xor_sync(0xffffffffu, s, o);
            if (lane == 0) {
                float sig = s / (1.f + expf(-s));
                ews[wid] = sig * g_tw[m * TOPK + wid];
            }
        }
        __syncthreads();

        float4 acc = make_float4(0.f, 0.f, 0.f, 0.f);
        #pragma unroll
        for (int k = 0; k < TOPK; k++) {
            int e = g_tidx[m * TOPK + k];
            float w = ews[k];
            float4 u = ((const float4*)(up_e + (size_t)e * HID))[tid];
            acc.x = fmaf(w, u.x, acc.x);
            acc.y = fmaf(w, u.y, acc.y);
            acc.z = fmaf(w, u.z, acc.z);
            acc.w = fmaf(w, u.w, acc.w);
        }
        float* dst = out + (size_t)m * HID + tid * 4;
        atomicAdd(dst + 0, acc.x);
        atomicAdd(dst + 1, acc.y);
        atomicAdd(dst + 2, acc.z);
        atomicAdd(dst + 3, acc.w);
    }
}

// ---------------- launch ----------------
static void* sym(const void* s) { void* p = nullptr; cudaGetSymbolAddress(&p, s); return p; }

extern "C" void kernel_launch(void* const* d_in, const int* in_sizes, int n_in,
                              void* d_out, int out_size)
{
    const float* X        = (const float*)d_in[0];
    const float* w_gate   = (const float*)d_in[1];
    const float* w_up     = (const float*)d_in[2];
    const float* w_down   = (const float*)d_in[3];
    const float* w_router = (const float*)d_in[4];
    const float* down_e   = (const float*)d_in[5];
    const float* up_e     = (const float*)d_in[6];

    float* out    = (float*)d_out;
    float* logits = (float*)d_out + (size_t)NTOK * HID;

    u16 *Xh = (u16*)sym(g_Xh),  *Xl = (u16*)sym(g_Xl);
    u16 *Wgh = (u16*)sym(g_Wgh);
    u16 *Wuh = (u16*)sym(g_Wuh);
    u16 *Wdh = (u16*)sym(g_Wdh);
    u16 *Wrh = (u16*)sym(g_Wrh), *Wrl = (u16*)sym(g_Wrl);
    u16 *Hh = (u16*)sym(g_Hh);

    cudaFuncSetAttribute(mega_kernel, cudaFuncAttributeMaxDynamicSharedMemorySize, SMEM_MEGA);

    // 0) splits + zero-out + counter reset
    split_all_kernel<<<8224, 256>>>(X, w_router, w_gate, w_up, w_down,
                                    Xh, Xl, Wrh, Wrl, Wgh, Wuh, Wdh, out);
    // 1) router + GU + routing + down + experts, ID-ordered dataflow
    mega_kernel<<<6480, 256, SMEM_MEGA>>>(Xh, Xl, Wgh, Wuh, Wrh, Wrl,
                                          Hh, logits, out, X, down_e, up_e);
    (void)in_sizes; (void)n_in; (void)out_size;
}